// round 4
// baseline (speedup 1.0000x reference)
#include <cuda_runtime.h>

#define NN 100000
#define NE 1600000
#define HH 128
#define ZC 20     // padded Z columns (19 used)
#define NCOLS 19
#define TPAD 132  // smem row pad

// ---- scratch (device globals: allocation-free) ----
__device__ __align__(16) float g_deg[NN];
__device__ __align__(16) float g_dinv[NN];                 // deg^-1/2
__device__ __align__(16) float g_y[NN * HH];               // y = A_hat x
__device__ __align__(16) float g_Z[NN * ZC];               // fused h1_k @ M_k, 19 cols
__device__ __align__(16) float g_P[NN * ZC];               // pre-softmax logits
__device__ __align__(16) float g_M[HH * ZC];               // M[h][col] = (W_k R_k^T)
__device__ __align__(16) float g_c[ZC];                    // fused bias per column

// ---- degree ----
__global__ void k_init_deg() {
    int i = blockIdx.x * blockDim.x + threadIdx.x;
    if (i < NN) g_deg[i] = 1.0f;  // self-loop
}

__global__ void k_deg(const int* __restrict__ ei) {
    int e = blockIdx.x * blockDim.x + threadIdx.x;
    if (e < NE) {
        int d = ei[NE + e];
        atomicAdd(&g_deg[d], 1.0f);
    }
}

__global__ void k_dinv() {
    int i = blockIdx.x * blockDim.x + threadIdx.x;
    if (i < NN) g_dinv[i] = rsqrtf(g_deg[i]);
}

// ---- y = A_hat x : self-loop term ----
__global__ void k_y_init(const float4* __restrict__ x4) {
    int idx = blockIdx.x * blockDim.x + threadIdx.x;
    if (idx >= NN * (HH / 4)) return;
    int n = idx >> 5;
    float di = g_dinv[n];
    float invd = di * di;
    float4 v = x4[idx];
    v.x *= invd; v.y *= invd; v.z *= invd; v.w *= invd;
    ((float4*)g_y)[idx] = v;
}

// ---- y = A_hat x : edge messages (one warp per edge, 128 floats) ----
__global__ void k_agg_y(const float4* __restrict__ x4, const int* __restrict__ ei) {
    int gw = (blockIdx.x * blockDim.x + threadIdx.x) >> 5;
    int lane = threadIdx.x & 31;
    if (gw >= NE) return;
    int s = ei[gw];
    int d = ei[NE + gw];
    float w = g_dinv[s] * g_dinv[d];
    float4 v = x4[s * 32 + lane];
    float* p = &g_y[d * HH + lane * 4];
    atomicAdd(p + 0, v.x * w);
    atomicAdd(p + 1, v.y * w);
    atomicAdd(p + 2, v.z * w);
    atomicAdd(p + 3, v.w * w);
}

// ---- precompute M_k = W_k R_k^T and c_k = b_k R_k^T + r_k ----
__global__ void k_mc(const float* __restrict__ gw_, const float* __restrict__ gb,
                     const float* __restrict__ r3w, const float* __restrict__ r3b,
                     const float* __restrict__ r2w, const float* __restrict__ r2b) {
    int t = blockIdx.x * blockDim.x + threadIdx.x;
    if (t >= NCOLS * HH) return;
    int col = t / HH, h = t % HH;
    int k; const float* R; float rb;
    if (col < 15) {
        k = col / 3; int c = col % 3;
        R = r3w + (k * 3 + c) * HH;
        rb = r3b[k * 3 + c];
    } else {
        int cc = col - 15; k = 5 + cc / 2; int c = cc % 2;
        R = r2w + ((k - 5) * 2 + c) * HH;
        rb = r2b[(k - 5) * 2 + c];
    }
    const float* Wrow = gw_ + k * HH * HH + h * HH;
    float acc = 0.f;
    #pragma unroll 8
    for (int j = 0; j < HH; j++) acc = fmaf(Wrow[j], R[j], acc);
    g_M[h * ZC + col] = acc;
    if (h == 0) {
        const float* b = gb + k * HH;
        float cb = 0.f;
        #pragma unroll 8
        for (int j = 0; j < HH; j++) cb = fmaf(b[j], R[j], cb);
        g_c[col] = cb + rb;
    }
    if (t == 0) g_c[19] = 0.f;
}

// ---- fused per-branch: h1 = relu(y W_k + b_k), Z[:,cols_k] = h1 @ M_k ----
// 128-node tile per block, 256 threads, 8x8 register micro-tiles.
__global__ void k_branch(const float* __restrict__ gw_, const float* __restrict__ gb) {
    extern __shared__ float sm[];
    float* yT   = sm;                 // [HH][TPAD] : y tile transposed (feat-major)
    float* ws   = yT + HH * TPAD;     // [HH][TPAD] : W_k, then reused as h1^T
    float* Ms   = ws + HH * TPAD;     // [HH][ZC]
    float* zbuf = Ms + HH * ZC;       // [128][3]

    int tid = threadIdx.x;
    int n0 = blockIdx.x * 128;

    // load y tile transposed (coalesced global read)
    for (int idx = tid; idx < 128 * HH; idx += 256) {
        int n = idx >> 7, h = idx & 127;
        float v = (n0 + n < NN) ? g_y[(n0 + n) * HH + h] : 0.f;
        yT[h * TPAD + n] = v;
    }
    for (int idx = tid; idx < HH * ZC; idx += 256) Ms[idx] = g_M[idx];

    int tx = tid & 15, ty = tid >> 4;
    int r0 = ty * 8, c0 = tx * 8;
    int node = tid & 127, half = tid >> 7, f0 = half * 64;

    for (int k = 0; k < 7; k++) {
        __syncthreads();
        // load W_k [h][f]
        const float* W = gw_ + k * HH * HH;
        for (int idx = tid; idx < HH * HH; idx += 256)
            ws[(idx >> 7) * TPAD + (idx & 127)] = W[idx];
        __syncthreads();

        // phase 1: h1[r0..r0+7][c0..c0+7] = y @ W + b
        float acc[8][8];
        #pragma unroll
        for (int j = 0; j < 8; j++) {
            float b = gb[k * HH + c0 + j];
            #pragma unroll
            for (int i = 0; i < 8; i++) acc[i][j] = b;
        }
        for (int kk = 0; kk < HH; kk++) {
            float a[8], b[8];
            #pragma unroll
            for (int i = 0; i < 8; i++) a[i] = yT[kk * TPAD + r0 + i];
            #pragma unroll
            for (int j = 0; j < 8; j++) b[j] = ws[kk * TPAD + c0 + j];
            #pragma unroll
            for (int i = 0; i < 8; i++)
                #pragma unroll
                for (int j = 0; j < 8; j++)
                    acc[i][j] = fmaf(a[i], b[j], acc[i][j]);
        }
        __syncthreads();
        // store relu(h1) transposed: h1T[feat][node] (reuse ws)
        #pragma unroll
        for (int i = 0; i < 8; i++)
            #pragma unroll
            for (int j = 0; j < 8; j++)
                ws[(c0 + j) * TPAD + (r0 + i)] = fmaxf(acc[i][j], 0.f);
        __syncthreads();

        // phase 2: z[node][c] = sum_f relu_h1[f][node] * M[f][c]
        int colbase = (k < 5) ? 3 * k : 15 + 2 * (k - 5);
        int ncol = (k < 5) ? 3 : 2;
        float z0 = 0.f, z1 = 0.f, z2 = 0.f;
        #pragma unroll 4
        for (int f = f0; f < f0 + 64; f++) {
            float hv = ws[f * TPAD + node];
            const float* m = &Ms[f * ZC + colbase];
            z0 = fmaf(hv, m[0], z0);
            z1 = fmaf(hv, m[1], z1);
            if (ncol == 3) z2 = fmaf(hv, m[2], z2);
        }
        if (half) { zbuf[node * 3] = z0; zbuf[node * 3 + 1] = z1; zbuf[node * 3 + 2] = z2; }
        __syncthreads();
        if (!half && (n0 + node) < NN) {
            float* zp = &g_Z[(n0 + node) * ZC + colbase];
            zp[0] = z0 + zbuf[node * 3];
            zp[1] = z1 + zbuf[node * 3 + 1];
            if (ncol == 3) zp[2] = z2 + zbuf[node * 3 + 2];
            if (k == 6) g_Z[(n0 + node) * ZC + 19] = 0.f;
        }
    }
}

// ---- P init: self-loop term + fused bias ----
__global__ void k_p_init() {
    int idx = blockIdx.x * blockDim.x + threadIdx.x;
    if (idx >= NN * 5) return;
    int n = idx / 5, ch = idx % 5;
    float di = g_dinv[n];
    float invd = di * di;
    float4 z = ((const float4*)g_Z)[idx];
    float4 c = ((const float4*)g_c)[ch];
    float4 p;
    p.x = fmaf(z.x, invd, c.x);
    p.y = fmaf(z.y, invd, c.y);
    p.z = fmaf(z.z, invd, c.z);
    p.w = fmaf(z.w, invd, c.w);
    ((float4*)g_P)[idx] = p;
}

// ---- narrow edge aggregation on Z (20 floats / edge, 4 threads/edge) ----
__global__ void k_agg_z(const int* __restrict__ ei) {
    int t = blockIdx.x * blockDim.x + threadIdx.x;
    int e = t >> 2;            // 4 threads per edge
    int q = t & 3;             // each handles 5 columns
    if (e >= NE) return;
    int s = ei[e];
    int d = ei[NE + e];
    float w = g_dinv[s] * g_dinv[d];
    const float* zs = &g_Z[s * ZC + q * 5];
    float* pd = &g_P[d * ZC + q * 5];
    #pragma unroll
    for (int c = 0; c < 5; c++)
        atomicAdd(pd + c, zs[c] * w);
}

// ---- fused softmax + write concatenated tuple output ----
__global__ void k_softmax(float* __restrict__ out) {
    int n = blockIdx.x * blockDim.x + threadIdx.x;
    if (n >= NN) return;
    float p[20];
    const float4* pr = (const float4*)&g_P[n * ZC];
    #pragma unroll
    for (int ch = 0; ch < 5; ch++) {
        float4 v = pr[ch];
        p[ch * 4] = v.x; p[ch * 4 + 1] = v.y; p[ch * 4 + 2] = v.z; p[ch * 4 + 3] = v.w;
    }
    #pragma unroll
    for (int k = 0; k < 5; k++) {
        float a = p[3 * k], b = p[3 * k + 1], c = p[3 * k + 2];
        float m = fmaxf(a, fmaxf(b, c));
        float ea = __expf(a - m), eb = __expf(b - m), ec = __expf(c - m);
        float inv = 1.f / (ea + eb + ec);
        long base = (long)(3 * k) * NN + (long)n * 3;
        out[base] = ea * inv; out[base + 1] = eb * inv; out[base + 2] = ec * inv;
    }
    #pragma unroll
    for (int k = 0; k < 2; k++) {
        float a = p[15 + 2 * k], b = p[15 + 2 * k + 1];
        float m = fmaxf(a, b);
        float ea = __expf(a - m), eb = __expf(b - m);
        float inv = 1.f / (ea + eb);
        long base = (long)(15 + 2 * k) * NN + (long)n * 2;
        out[base] = ea * inv; out[base + 1] = eb * inv;
    }
}

extern "C" void kernel_launch(void* const* d_in, const int* in_sizes, int n_in,
                              void* d_out, int out_size) {
    const float* x   = (const float*)d_in[0];
    const int*   ei  = (const int*)d_in[1];     // edge_index is int32 (JAX x64 disabled)
    const float* gw_ = (const float*)d_in[2];
    const float* gb  = (const float*)d_in[3];
    const float* r3w = (const float*)d_in[4];
    const float* r3b = (const float*)d_in[5];
    const float* r2w = (const float*)d_in[6];
    const float* r2b = (const float*)d_in[7];
    float* out = (float*)d_out;

    static int smem_set = 0;
    int smem = (HH * TPAD * 2 + HH * ZC + 128 * 3) * (int)sizeof(float);
    if (!smem_set) {
        cudaFuncSetAttribute(k_branch, cudaFuncAttributeMaxDynamicSharedMemorySize, smem);
        smem_set = 1;
    }

    k_init_deg<<<(NN + 255) / 256, 256>>>();
    k_deg<<<(NE + 255) / 256, 256>>>(ei);
    k_dinv<<<(NN + 255) / 256, 256>>>();
    k_y_init<<<(NN * 32 + 255) / 256, 256>>>((const float4*)x);
    k_mc<<<(NCOLS * HH + 127) / 128, 128>>>(gw_, gb, r3w, r3b, r2w, r2b);
    k_agg_y<<<NE / 8, 256>>>((const float4*)x, ei);
    k_branch<<<(NN + 127) / 128, 256, smem>>>(gw_, gb);
    k_p_init<<<(NN * 5 + 255) / 256, 256>>>();
    k_agg_z<<<(NE * 4 + 255) / 256, 256>>>(ei);
    k_softmax<<<(NN + 255) / 256, 256>>>(out);
}

// round 6
// speedup vs baseline: 2.3134x; 2.3134x over previous
#include <cuda_runtime.h>
#include <cuda_fp16.h>
#include <cstdint>

#define NN 100000
#define NE 1600000
#define HH 128
#define ZC 20
#define NB 782            // ceil(NN/128)
#define PITCH 136         // smem row pitch in halves (272B, conflict-free for ldmatrix)
#define TILE_GB 32768     // one 128x128 fp16 tile in global bytes (unpadded)

// ---- scratch (device globals: allocation-free) ----
__device__ __align__(16) float g_deg[NN];
__device__ __align__(16) float g_dinv[NN];
__device__ __align__(16) float g_y[NN * HH];
__device__ __align__(16) float g_Z[NN * ZC];
__device__ __align__(16) float g_P[NN * ZC];
__device__ __align__(16) float g_M[HH * ZC];
__device__ __align__(16) float g_c[ZC];
__device__ __align__(16) unsigned char g_Wh[7 * TILE_GB];  // W^T hi fp16, [f][h] row-major
__device__ __align__(16) unsigned char g_Wl[7 * TILE_GB];  // W^T lo
__device__ __align__(16) float g_BM[7 * HH * 4];           // {bias, M0, M1, M2} per (k,f)

__device__ __forceinline__ uint32_t smem_u32(const void* p) {
    uint32_t a;
    asm("{ .reg .u64 t; cvta.to.shared.u64 t, %1; cvt.u32.u64 %0, t; }" : "=r"(a) : "l"(p));
    return a;
}
__device__ __forceinline__ void red_add_v4(float* addr, float a, float b, float c, float d) {
    asm volatile("red.global.add.v4.f32 [%0], {%1,%2,%3,%4};"
                 :: "l"(addr), "f"(a), "f"(b), "f"(c), "f"(d) : "memory");
}

// ================= graph prep =================
__global__ void k_init_deg() {
    int i = blockIdx.x * blockDim.x + threadIdx.x;
    if (i < NN) g_deg[i] = 1.0f;
}
__global__ void k_deg(const int* __restrict__ ei) {
    int e = blockIdx.x * blockDim.x + threadIdx.x;
    if (e < NE) atomicAdd(&g_deg[ei[NE + e]], 1.0f);
}
__global__ void k_dinv() {
    int i = blockIdx.x * blockDim.x + threadIdx.x;
    if (i < NN) g_dinv[i] = rsqrtf(g_deg[i]);
}
__global__ void k_y_init(const float4* __restrict__ x4) {
    int idx = blockIdx.x * blockDim.x + threadIdx.x;
    if (idx >= NN * (HH / 4)) return;
    int n = idx >> 5;
    float di = g_dinv[n];
    float invd = di * di;
    float4 v = x4[idx];
    v.x *= invd; v.y *= invd; v.z *= invd; v.w *= invd;
    ((float4*)g_y)[idx] = v;
}
__global__ void k_agg_y(const float4* __restrict__ x4, const int* __restrict__ ei) {
    int gw = (blockIdx.x * blockDim.x + threadIdx.x) >> 5;
    int lane = threadIdx.x & 31;
    if (gw >= NE) return;
    int s = ei[gw];
    int d = ei[NE + gw];
    float w = g_dinv[s] * g_dinv[d];
    float4 v = x4[s * 32 + lane];
    red_add_v4(&g_y[d * HH + lane * 4], v.x * w, v.y * w, v.z * w, v.w * w);
}

// ---- M_k = W_k R_k^T, c_k = b_k R_k^T + r_k ----
__global__ void k_mc(const float* __restrict__ gw_, const float* __restrict__ gb,
                     const float* __restrict__ r3w, const float* __restrict__ r3b,
                     const float* __restrict__ r2w, const float* __restrict__ r2b) {
    int t = blockIdx.x * blockDim.x + threadIdx.x;
    if (t >= 19 * HH) return;
    int col = t / HH, h = t % HH;
    int k; const float* R; float rb;
    if (col < 15) { k = col / 3; int c = col % 3; R = r3w + (k * 3 + c) * HH; rb = r3b[k * 3 + c]; }
    else { int cc = col - 15; k = 5 + cc / 2; int c = cc % 2; R = r2w + ((k - 5) * 2 + c) * HH; rb = r2b[(k - 5) * 2 + c]; }
    const float* Wrow = gw_ + k * HH * HH + h * HH;
    float acc = 0.f;
    #pragma unroll 8
    for (int j = 0; j < HH; j++) acc = fmaf(Wrow[j], R[j], acc);
    g_M[h * ZC + col] = acc;
    if (h == 0) {
        const float* b = gb + k * HH;
        float cb = 0.f;
        #pragma unroll 8
        for (int j = 0; j < HH; j++) cb = fmaf(b[j], R[j], cb);
        g_c[col] = cb + rb;
    }
    if (t == 0) g_c[19] = 0.f;
}

// ---- W^T -> fp16 hi/lo tiles, [f][h] row-major (B operand) ----
__global__ void k_prep_w(const float* __restrict__ gw_) {
    int t = blockIdx.x * blockDim.x + threadIdx.x;
    if (t >= 7 * 128 * 64) return;
    int k = t / 8192, r = t % 8192, f = r / 64, h = (r % 64) * 2;
    float w0 = gw_[k * 16384 + h * 128 + f];
    float w1 = gw_[k * 16384 + (h + 1) * 128 + f];
    __half h0 = __float2half_rn(w0), h1 = __float2half_rn(w1);
    __half l0 = __float2half_rn(w0 - __half2float(h0));
    __half l1 = __float2half_rn(w1 - __half2float(h1));
    int off = f * 256 + h * 2;
    *(uint32_t*)(g_Wh + k * TILE_GB + off) =
        ((uint32_t)__half_as_ushort(h1) << 16) | __half_as_ushort(h0);
    *(uint32_t*)(g_Wl + k * TILE_GB + off) =
        ((uint32_t)__half_as_ushort(l1) << 16) | __half_as_ushort(l0);
}

__global__ void k_prep_bm(const float* __restrict__ gb) {
    int t = blockIdx.x * blockDim.x + threadIdx.x;
    if (t >= 7 * HH) return;
    int k = t >> 7, f = t & 127;
    int colbase = (k < 5) ? 3 * k : 15 + 2 * (k - 5);
    int ncol = (k < 5) ? 3 : 2;
    float4 v;
    v.x = gb[k * HH + f];
    v.y = g_M[f * ZC + colbase];
    v.z = g_M[f * ZC + colbase + 1];
    v.w = (ncol == 3) ? g_M[f * ZC + colbase + 2] : 0.f;
    ((float4*)g_BM)[t] = v;
}

// ================= HMMA branch kernel =================
// 128 nodes x 128 feats per CTA, 256 threads (8 warps), warp w owns rows w*16..+15.
// D = y @ W_k via mma.sync m16n8k16 fp16 split-precision, fp32 reg accumulators.
__global__ void __launch_bounds__(256) k_branch() {
    extern __shared__ __align__(16) unsigned char sm[];
    const int A_HI = 0;
    const int A_LO = A_HI + 128 * PITCH * 2;     // 34816
    const int B_HI = A_LO + 128 * PITCH * 2;
    const int B_LO = B_HI + 128 * PITCH * 2;
    const int BM_OFF = B_LO + 128 * PITCH * 2;   // 139264
    uint32_t sb = smem_u32(sm);
    int tid = threadIdx.x;
    int w = tid >> 5, lane = tid & 31;
    int n0 = blockIdx.x * 128;

    // ---- convert y tile -> fp16 hi/lo into padded smem ----
    for (int idx = tid; idx < 128 * 64; idx += 256) {
        int row = idx >> 6, col = (idx & 63) * 2;
        float v0 = 0.f, v1 = 0.f;
        if (n0 + row < NN) {
            float2 p = *(const float2*)&g_y[(size_t)(n0 + row) * HH + col];
            v0 = p.x; v1 = p.y;
        }
        __half h0 = __float2half_rn(v0), h1 = __float2half_rn(v1);
        __half l0 = __float2half_rn(v0 - __half2float(h0));
        __half l1 = __float2half_rn(v1 - __half2float(h1));
        int off = row * (PITCH * 2) + col * 2;
        *(uint32_t*)(sm + A_HI + off) = ((uint32_t)__half_as_ushort(h1) << 16) | __half_as_ushort(h0);
        *(uint32_t*)(sm + A_LO + off) = ((uint32_t)__half_as_ushort(l1) << 16) | __half_as_ushort(l0);
    }
    {
        const uint4* src = (const uint4*)g_BM;
        uint4* dst = (uint4*)(sm + BM_OFF);
        for (int i = tid; i < 7 * HH; i += 256) dst[i] = src[i];
    }

    // ldmatrix lane addresses (row within 16-row tile, 8-col block select)
    int a_row = lane & 15, a_cb = (lane >> 4) * 8;          // A: x4 over 16x16
    int b_row = ((lane >> 4) * 8) + (lane & 7);             // B: x4 over two 8x16 n-tiles
    int b_kb = ((lane >> 3) & 1) * 8;
    const float4* bmt = (const float4*)(sm + BM_OFF);

    for (int k = 0; k < 7; k++) {
        __syncthreads();   // prior branch's smem reads done
        {   // load W_k hi/lo into padded smem rows
            const uint4* sh = (const uint4*)(g_Wh + k * TILE_GB);
            const uint4* sl = (const uint4*)(g_Wl + k * TILE_GB);
            for (int i = tid; i < 2048; i += 256) {
                int f = i >> 4, seg = i & 15;
                int off = f * (PITCH * 2) + seg * 16;
                *(uint4*)(sm + B_HI + off) = sh[i];
                *(uint4*)(sm + B_LO + off) = sl[i];
            }
        }
        __syncthreads();

        float acc[16][4];
        #pragma unroll
        for (int t = 0; t < 16; t++)
            #pragma unroll
            for (int j = 0; j < 4; j++) acc[t][j] = 0.f;

        #pragma unroll
        for (int pass = 0; pass < 3; pass++) {
            uint32_t Ab = sb + ((pass == 2) ? A_LO : A_HI);
            uint32_t Bb = sb + ((pass == 1) ? B_LO : B_HI);
            #pragma unroll
            for (int ks = 0; ks < 8; ks++) {
                uint32_t a0, a1, a2, a3;
                uint32_t aaddr = Ab + (w * 16 + a_row) * (PITCH * 2) + (ks * 16 + a_cb) * 2;
                asm volatile("ldmatrix.sync.aligned.m8n8.x4.shared.b16 {%0,%1,%2,%3}, [%4];"
                             : "=r"(a0), "=r"(a1), "=r"(a2), "=r"(a3) : "r"(aaddr));
                #pragma unroll
                for (int p = 0; p < 8; p++) {
                    uint32_t b0, b1, b2, b3;
                    uint32_t baddr = Bb + (p * 16 + b_row) * (PITCH * 2) + (ks * 16 + b_kb) * 2;
                    asm volatile("ldmatrix.sync.aligned.m8n8.x4.shared.b16 {%0,%1,%2,%3}, [%4];"
                                 : "=r"(b0), "=r"(b1), "=r"(b2), "=r"(b3) : "r"(baddr));
                    asm volatile(
                        "mma.sync.aligned.m16n8k16.row.col.f32.f16.f16.f32 "
                        "{%0,%1,%2,%3}, {%4,%5,%6,%7}, {%8,%9}, {%0,%1,%2,%3};"
                        : "+f"(acc[2*p][0]), "+f"(acc[2*p][1]), "+f"(acc[2*p][2]), "+f"(acc[2*p][3])
                        : "r"(a0), "r"(a1), "r"(a2), "r"(a3), "r"(b0), "r"(b1));
                    asm volatile(
                        "mma.sync.aligned.m16n8k16.row.col.f32.f16.f16.f32 "
                        "{%0,%1,%2,%3}, {%4,%5,%6,%7}, {%8,%9}, {%0,%1,%2,%3};"
                        : "+f"(acc[2*p+1][0]), "+f"(acc[2*p+1][1]), "+f"(acc[2*p+1][2]), "+f"(acc[2*p+1][3])
                        : "r"(a0), "r"(a1), "r"(a2), "r"(a3), "r"(b2), "r"(b3));
                }
            }
        }

        // ---- epilogue: bias + relu + readout dot, 4-lane reduce ----
        int gr = lane >> 2, cq = (lane & 3) * 2;
        float zA0 = 0.f, zA1 = 0.f, zA2 = 0.f, zB0 = 0.f, zB1 = 0.f, zB2 = 0.f;
        #pragma unroll
        for (int nt = 0; nt < 16; nt++) {
            float4 m0 = bmt[k * HH + nt * 8 + cq];
            float4 m1 = bmt[k * HH + nt * 8 + cq + 1];
            float hA0 = fmaxf(acc[nt][0] + m0.x, 0.f);
            float hA1 = fmaxf(acc[nt][1] + m1.x, 0.f);
            float hB0 = fmaxf(acc[nt][2] + m0.x, 0.f);
            float hB1 = fmaxf(acc[nt][3] + m1.x, 0.f);
            zA0 = fmaf(hA0, m0.y, fmaf(hA1, m1.y, zA0));
            zA1 = fmaf(hA0, m0.z, fmaf(hA1, m1.z, zA1));
            zA2 = fmaf(hA0, m0.w, fmaf(hA1, m1.w, zA2));
            zB0 = fmaf(hB0, m0.y, fmaf(hB1, m1.y, zB0));
            zB1 = fmaf(hB0, m0.z, fmaf(hB1, m1.z, zB1));
            zB2 = fmaf(hB0, m0.w, fmaf(hB1, m1.w, zB2));
        }
        #pragma unroll
        for (int off = 1; off < 4; off <<= 1) {
            zA0 += __shfl_xor_sync(0xffffffffu, zA0, off);
            zA1 += __shfl_xor_sync(0xffffffffu, zA1, off);
            zA2 += __shfl_xor_sync(0xffffffffu, zA2, off);
            zB0 += __shfl_xor_sync(0xffffffffu, zB0, off);
            zB1 += __shfl_xor_sync(0xffffffffu, zB1, off);
            zB2 += __shfl_xor_sync(0xffffffffu, zB2, off);
        }
        if ((lane & 3) == 0) {
            int colbase = (k < 5) ? 3 * k : 15 + 2 * (k - 5);
            int ncol = (k < 5) ? 3 : 2;
            int rowA = n0 + w * 16 + gr, rowB = rowA + 8;
            if (rowA < NN) {
                float* zp = &g_Z[(size_t)rowA * ZC + colbase];
                zp[0] = zA0; zp[1] = zA1;
                if (ncol == 3) zp[2] = zA2;
                if (k == 6) g_Z[(size_t)rowA * ZC + 19] = 0.f;
            }
            if (rowB < NN) {
                float* zp = &g_Z[(size_t)rowB * ZC + colbase];
                zp[0] = zB0; zp[1] = zB1;
                if (ncol == 3) zp[2] = zB2;
                if (k == 6) g_Z[(size_t)rowB * ZC + 19] = 0.f;
            }
        }
    }
}

// ================= tail =================
__global__ void k_p_init() {
    int idx = blockIdx.x * blockDim.x + threadIdx.x;
    if (idx >= NN * 5) return;
    int n = idx / 5, ch = idx % 5;
    float di = g_dinv[n];
    float invd = di * di;
    float4 z = ((const float4*)g_Z)[idx];
    float4 c = ((const float4*)g_c)[ch];
    float4 p;
    p.x = fmaf(z.x, invd, c.x);
    p.y = fmaf(z.y, invd, c.y);
    p.z = fmaf(z.z, invd, c.z);
    p.w = fmaf(z.w, invd, c.w);
    ((float4*)g_P)[idx] = p;
}

__global__ void k_agg_z(const int* __restrict__ ei) {
    int e = blockIdx.x * blockDim.x + threadIdx.x;
    if (e >= NE) return;
    int s = ei[e];
    int d = ei[NE + e];
    float w = g_dinv[s] * g_dinv[d];
    const float4* zs = (const float4*)&g_Z[s * ZC];
    float* pd = &g_P[d * ZC];
    #pragma unroll
    for (int c = 0; c < 5; c++) {
        float4 v = zs[c];
        red_add_v4(pd + c * 4, v.x * w, v.y * w, v.z * w, v.w * w);
    }
}

__global__ void k_softmax(float* __restrict__ out) {
    int n = blockIdx.x * blockDim.x + threadIdx.x;
    if (n >= NN) return;
    float p[20];
    const float4* pr = (const float4*)&g_P[n * ZC];
    #pragma unroll
    for (int ch = 0; ch < 5; ch++) {
        float4 v = pr[ch];
        p[ch * 4] = v.x; p[ch * 4 + 1] = v.y; p[ch * 4 + 2] = v.z; p[ch * 4 + 3] = v.w;
    }
    #pragma unroll
    for (int k = 0; k < 5; k++) {
        float a = p[3 * k], b = p[3 * k + 1], c = p[3 * k + 2];
        float m = fmaxf(a, fmaxf(b, c));
        float ea = __expf(a - m), eb = __expf(b - m), ec = __expf(c - m);
        float inv = 1.f / (ea + eb + ec);
        long base = (long)(3 * k) * NN + (long)n * 3;
        out[base] = ea * inv; out[base + 1] = eb * inv; out[base + 2] = ec * inv;
    }
    #pragma unroll
    for (int k = 0; k < 2; k++) {
        float a = p[15 + 2 * k], b = p[15 + 2 * k + 1];
        float m = fmaxf(a, b);
        float ea = __expf(a - m), eb = __expf(b - m);
        float inv = 1.f / (ea + eb);
        long base = (long)(15 + 2 * k) * NN + (long)n * 2;
        out[base] = ea * inv; out[base + 1] = eb * inv;
    }
}

extern "C" void kernel_launch(void* const* d_in, const int* in_sizes, int n_in,
                              void* d_out, int out_size) {
    const float* x   = (const float*)d_in[0];
    const int*   ei  = (const int*)d_in[1];
    const float* gw_ = (const float*)d_in[2];
    const float* gb  = (const float*)d_in[3];
    const float* r3w = (const float*)d_in[4];
    const float* r3b = (const float*)d_in[5];
    const float* r2w = (const float*)d_in[6];
    const float* r2b = (const float*)d_in[7];
    float* out = (float*)d_out;

    const int SMEM = 4 * 128 * PITCH * 2 + 7 * HH * 16;   // 153600
    static int once = 0;
    if (!once) {
        cudaFuncSetAttribute(k_branch, cudaFuncAttributeMaxDynamicSharedMemorySize, SMEM);
        once = 1;
    }

    k_init_deg<<<(NN + 255) / 256, 256>>>();
    k_deg<<<(NE + 255) / 256, 256>>>(ei);
    k_dinv<<<(NN + 255) / 256, 256>>>();
    k_y_init<<<(NN * 32 + 255) / 256, 256>>>((const float4*)x);
    k_mc<<<(19 * HH + 127) / 128, 128>>>(gw_, gb, r3w, r3b, r2w, r2b);
    k_prep_w<<<(7 * 128 * 64 + 127) / 128, 128>>>(gw_);
    k_prep_bm<<<(7 * HH + 127) / 128, 128>>>(gb);
    k_agg_y<<<NE / 8, 256>>>((const float4*)x, ei);
    k_branch<<<NB, 256, SMEM>>>();
    k_p_init<<<(NN * 5 + 255) / 256, 256>>>();
    k_agg_z<<<(NE + 255) / 256, 256>>>(ei);
    k_softmax<<<(NN + 255) / 256, 256>>>(out);
}

// round 7
// speedup vs baseline: 2.5754x; 1.1132x over previous
#include <cuda_runtime.h>
#include <cuda_fp16.h>
#include <cstdint>

#define NN 100000
#define NE 1600000
#define HH 128
#define ZC 20
#define NB 782            // ceil(NN/128)
#define PITCH 136         // smem row pitch in halves (272B, conflict-free for ldmatrix)
#define TILE_GB 32768     // one 128x128 fp16 tile in global bytes (unpadded)

// ---- scratch (device globals: allocation-free) ----
__device__ __align__(16) float g_deg[NN];
__device__ __align__(16) float g_dinv[NN];
__device__ __align__(16) float g_y[NN * HH];
__device__ __align__(16) float g_Z[NN * ZC];               // Z' = Z * dinv (pre-scaled)
__device__ __align__(16) float g_P[NN * ZC];               // accumulator, seeded with Z'
__device__ __align__(16) float g_M[HH * ZC];
__device__ __align__(16) float g_c[ZC];
__device__ __align__(16) unsigned char g_Wh[7 * TILE_GB];  // W^T hi fp16, [f][h] row-major
__device__ __align__(16) unsigned char g_Wl[7 * TILE_GB];  // W^T lo
__device__ __align__(16) float g_BM[7 * HH * 4];           // {bias, M0, M1, M2} per (k,f)

__device__ __forceinline__ uint32_t smem_u32(const void* p) {
    uint32_t a;
    asm("{ .reg .u64 t; cvta.to.shared.u64 t, %1; cvt.u32.u64 %0, t; }" : "=r"(a) : "l"(p));
    return a;
}
__device__ __forceinline__ void red_add_v4(float* addr, float a, float b, float c, float d) {
    asm volatile("red.global.add.v4.f32 [%0], {%1,%2,%3,%4};"
                 :: "l"(addr), "f"(a), "f"(b), "f"(c), "f"(d) : "memory");
}

// ================= graph prep =================
__global__ void k_init_deg() {
    int i = blockIdx.x * blockDim.x + threadIdx.x;
    if (i < NN) g_deg[i] = 1.0f;
}
__global__ void k_deg(const int4* __restrict__ dst4) {
    int t = blockIdx.x * blockDim.x + threadIdx.x;
    if (t >= NE / 4) return;
    int4 d = dst4[t];
    atomicAdd(&g_deg[d.x], 1.0f);
    atomicAdd(&g_deg[d.y], 1.0f);
    atomicAdd(&g_deg[d.z], 1.0f);
    atomicAdd(&g_deg[d.w], 1.0f);
}
__global__ void k_dinv() {
    int i = blockIdx.x * blockDim.x + threadIdx.x;
    if (i < NN) g_dinv[i] = rsqrtf(g_deg[i]);
}
__global__ void k_y_init(const float4* __restrict__ x4) {
    int idx = blockIdx.x * blockDim.x + threadIdx.x;
    if (idx >= NN * (HH / 4)) return;
    int n = idx >> 5;
    float di = g_dinv[n];
    float invd = di * di;
    float4 v = x4[idx];
    v.x *= invd; v.y *= invd; v.z *= invd; v.w *= invd;
    ((float4*)g_y)[idx] = v;
}
// 4 edges per warp: batch gathers for MLP, then fire REDs.
__global__ void k_agg_y(const float4* __restrict__ x4, const int* __restrict__ ei) {
    int warp = (blockIdx.x * blockDim.x + threadIdx.x) >> 5;
    int lane = threadIdx.x & 31;
    int e0 = warp * 4;
    if (e0 >= NE) return;
    int s0 = ei[e0], s1 = ei[e0 + 1], s2 = ei[e0 + 2], s3 = ei[e0 + 3];
    int d0 = ei[NE + e0], d1 = ei[NE + e0 + 1], d2 = ei[NE + e0 + 2], d3 = ei[NE + e0 + 3];
    float w0 = g_dinv[s0] * g_dinv[d0];
    float w1 = g_dinv[s1] * g_dinv[d1];
    float w2 = g_dinv[s2] * g_dinv[d2];
    float w3 = g_dinv[s3] * g_dinv[d3];
    float4 v0 = x4[s0 * 32 + lane];
    float4 v1 = x4[s1 * 32 + lane];
    float4 v2 = x4[s2 * 32 + lane];
    float4 v3 = x4[s3 * 32 + lane];
    red_add_v4(&g_y[d0 * HH + lane * 4], v0.x * w0, v0.y * w0, v0.z * w0, v0.w * w0);
    red_add_v4(&g_y[d1 * HH + lane * 4], v1.x * w1, v1.y * w1, v1.z * w1, v1.w * w1);
    red_add_v4(&g_y[d2 * HH + lane * 4], v2.x * w2, v2.y * w2, v2.z * w2, v2.w * w2);
    red_add_v4(&g_y[d3 * HH + lane * 4], v3.x * w3, v3.y * w3, v3.z * w3, v3.w * w3);
}

// ---- M_k = W_k R_k^T, c_k = b_k R_k^T + r_k ----
__global__ void k_mc(const float* __restrict__ gw_, const float* __restrict__ gb,
                     const float* __restrict__ r3w, const float* __restrict__ r3b,
                     const float* __restrict__ r2w, const float* __restrict__ r2b) {
    int t = blockIdx.x * blockDim.x + threadIdx.x;
    if (t >= 19 * HH) return;
    int col = t / HH, h = t % HH;
    int k; const float* R; float rb;
    if (col < 15) { k = col / 3; int c = col % 3; R = r3w + (k * 3 + c) * HH; rb = r3b[k * 3 + c]; }
    else { int cc = col - 15; k = 5 + cc / 2; int c = cc % 2; R = r2w + ((k - 5) * 2 + c) * HH; rb = r2b[(k - 5) * 2 + c]; }
    const float* Wrow = gw_ + k * HH * HH + h * HH;
    float acc = 0.f;
    #pragma unroll 8
    for (int j = 0; j < HH; j++) acc = fmaf(Wrow[j], R[j], acc);
    g_M[h * ZC + col] = acc;
    if (h == 0) {
        const float* b = gb + k * HH;
        float cb = 0.f;
        #pragma unroll 8
        for (int j = 0; j < HH; j++) cb = fmaf(b[j], R[j], cb);
        g_c[col] = cb + rb;
    }
    if (t == 0) g_c[19] = 0.f;
}

// ---- W^T -> fp16 hi/lo tiles, [f][h] row-major (B operand) ----
__global__ void k_prep_w(const float* __restrict__ gw_) {
    int t = blockIdx.x * blockDim.x + threadIdx.x;
    if (t >= 7 * 128 * 64) return;
    int k = t / 8192, r = t % 8192, f = r / 64, h = (r % 64) * 2;
    float w0 = gw_[k * 16384 + h * 128 + f];
    float w1 = gw_[k * 16384 + (h + 1) * 128 + f];
    __half h0 = __float2half_rn(w0), h1 = __float2half_rn(w1);
    __half l0 = __float2half_rn(w0 - __half2float(h0));
    __half l1 = __float2half_rn(w1 - __half2float(h1));
    int off = f * 256 + h * 2;
    *(uint32_t*)(g_Wh + k * TILE_GB + off) =
        ((uint32_t)__half_as_ushort(h1) << 16) | __half_as_ushort(h0);
    *(uint32_t*)(g_Wl + k * TILE_GB + off) =
        ((uint32_t)__half_as_ushort(l1) << 16) | __half_as_ushort(l0);
}

__global__ void k_prep_bm(const float* __restrict__ gb) {
    int t = blockIdx.x * blockDim.x + threadIdx.x;
    if (t >= 7 * HH) return;
    int k = t >> 7, f = t & 127;
    int colbase = (k < 5) ? 3 * k : 15 + 2 * (k - 5);
    int ncol = (k < 5) ? 3 : 2;
    float4 v;
    v.x = gb[k * HH + f];
    v.y = g_M[f * ZC + colbase];
    v.z = g_M[f * ZC + colbase + 1];
    v.w = (ncol == 3) ? g_M[f * ZC + colbase + 2] : 0.f;
    ((float4*)g_BM)[t] = v;
}

// ================= HMMA branch kernel =================
// 128 nodes x 128 feats per CTA, 256 threads (8 warps), warp w owns rows w*16..+15.
// D = y @ W_k via mma.sync m16n8k16 fp16 split-precision, fp32 reg accumulators.
// Epilogue writes Z' = (readout(relu(D+b))) * dinv[node] into BOTH g_Z and g_P.
__global__ void __launch_bounds__(256) k_branch() {
    extern __shared__ __align__(16) unsigned char sm[];
    const int A_HI = 0;
    const int A_LO = A_HI + 128 * PITCH * 2;
    const int B_HI = A_LO + 128 * PITCH * 2;
    const int B_LO = B_HI + 128 * PITCH * 2;
    const int BM_OFF = B_LO + 128 * PITCH * 2;
    uint32_t sb = smem_u32(sm);
    int tid = threadIdx.x;
    int w = tid >> 5, lane = tid & 31;
    int n0 = blockIdx.x * 128;

    // ---- convert y tile -> fp16 hi/lo into padded smem ----
    for (int idx = tid; idx < 128 * 64; idx += 256) {
        int row = idx >> 6, col = (idx & 63) * 2;
        float v0 = 0.f, v1 = 0.f;
        if (n0 + row < NN) {
            float2 p = *(const float2*)&g_y[(size_t)(n0 + row) * HH + col];
            v0 = p.x; v1 = p.y;
        }
        __half h0 = __float2half_rn(v0), h1 = __float2half_rn(v1);
        __half l0 = __float2half_rn(v0 - __half2float(h0));
        __half l1 = __float2half_rn(v1 - __half2float(h1));
        int off = row * (PITCH * 2) + col * 2;
        *(uint32_t*)(sm + A_HI + off) = ((uint32_t)__half_as_ushort(h1) << 16) | __half_as_ushort(h0);
        *(uint32_t*)(sm + A_LO + off) = ((uint32_t)__half_as_ushort(l1) << 16) | __half_as_ushort(l0);
    }
    {
        const uint4* src = (const uint4*)g_BM;
        uint4* dst = (uint4*)(sm + BM_OFF);
        for (int i = tid; i < 7 * HH; i += 256) dst[i] = src[i];
    }

    int a_row = lane & 15, a_cb = (lane >> 4) * 8;
    int b_row = ((lane >> 4) * 8) + (lane & 7);
    int b_kb = ((lane >> 3) & 1) * 8;
    const float4* bmt = (const float4*)(sm + BM_OFF);

    for (int k = 0; k < 7; k++) {
        __syncthreads();
        {
            const uint4* sh = (const uint4*)(g_Wh + k * TILE_GB);
            const uint4* sl = (const uint4*)(g_Wl + k * TILE_GB);
            for (int i = tid; i < 2048; i += 256) {
                int f = i >> 4, seg = i & 15;
                int off = f * (PITCH * 2) + seg * 16;
                *(uint4*)(sm + B_HI + off) = sh[i];
                *(uint4*)(sm + B_LO + off) = sl[i];
            }
        }
        __syncthreads();

        float acc[16][4];
        #pragma unroll
        for (int t = 0; t < 16; t++)
            #pragma unroll
            for (int j = 0; j < 4; j++) acc[t][j] = 0.f;

        #pragma unroll
        for (int pass = 0; pass < 3; pass++) {
            uint32_t Ab = sb + ((pass == 2) ? A_LO : A_HI);
            uint32_t Bb = sb + ((pass == 1) ? B_LO : B_HI);
            #pragma unroll
            for (int ks = 0; ks < 8; ks++) {
                uint32_t a0, a1, a2, a3;
                uint32_t aaddr = Ab + (w * 16 + a_row) * (PITCH * 2) + (ks * 16 + a_cb) * 2;
                asm volatile("ldmatrix.sync.aligned.m8n8.x4.shared.b16 {%0,%1,%2,%3}, [%4];"
                             : "=r"(a0), "=r"(a1), "=r"(a2), "=r"(a3) : "r"(aaddr));
                #pragma unroll
                for (int p = 0; p < 8; p++) {
                    uint32_t b0, b1, b2, b3;
                    uint32_t baddr = Bb + (p * 16 + b_row) * (PITCH * 2) + (ks * 16 + b_kb) * 2;
                    asm volatile("ldmatrix.sync.aligned.m8n8.x4.shared.b16 {%0,%1,%2,%3}, [%4];"
                                 : "=r"(b0), "=r"(b1), "=r"(b2), "=r"(b3) : "r"(baddr));
                    asm volatile(
                        "mma.sync.aligned.m16n8k16.row.col.f32.f16.f16.f32 "
                        "{%0,%1,%2,%3}, {%4,%5,%6,%7}, {%8,%9}, {%0,%1,%2,%3};"
                        : "+f"(acc[2*p][0]), "+f"(acc[2*p][1]), "+f"(acc[2*p][2]), "+f"(acc[2*p][3])
                        : "r"(a0), "r"(a1), "r"(a2), "r"(a3), "r"(b0), "r"(b1));
                    asm volatile(
                        "mma.sync.aligned.m16n8k16.row.col.f32.f16.f16.f32 "
                        "{%0,%1,%2,%3}, {%4,%5,%6,%7}, {%8,%9}, {%0,%1,%2,%3};"
                        : "+f"(acc[2*p+1][0]), "+f"(acc[2*p+1][1]), "+f"(acc[2*p+1][2]), "+f"(acc[2*p+1][3])
                        : "r"(a0), "r"(a1), "r"(a2), "r"(a3), "r"(b2), "r"(b3));
                }
            }
        }

        // ---- epilogue: bias + relu + readout dot, 4-lane reduce, pre-scale by dinv ----
        int gr = lane >> 2, cq = (lane & 3) * 2;
        float zA0 = 0.f, zA1 = 0.f, zA2 = 0.f, zB0 = 0.f, zB1 = 0.f, zB2 = 0.f;
        #pragma unroll
        for (int nt = 0; nt < 16; nt++) {
            float4 m0 = bmt[k * HH + nt * 8 + cq];
            float4 m1 = bmt[k * HH + nt * 8 + cq + 1];
            float hA0 = fmaxf(acc[nt][0] + m0.x, 0.f);
            float hA1 = fmaxf(acc[nt][1] + m1.x, 0.f);
            float hB0 = fmaxf(acc[nt][2] + m0.x, 0.f);
            float hB1 = fmaxf(acc[nt][3] + m1.x, 0.f);
            zA0 = fmaf(hA0, m0.y, fmaf(hA1, m1.y, zA0));
            zA1 = fmaf(hA0, m0.z, fmaf(hA1, m1.z, zA1));
            zA2 = fmaf(hA0, m0.w, fmaf(hA1, m1.w, zA2));
            zB0 = fmaf(hB0, m0.y, fmaf(hB1, m1.y, zB0));
            zB1 = fmaf(hB0, m0.z, fmaf(hB1, m1.z, zB1));
            zB2 = fmaf(hB0, m0.w, fmaf(hB1, m1.w, zB2));
        }
        #pragma unroll
        for (int off = 1; off < 4; off <<= 1) {
            zA0 += __shfl_xor_sync(0xffffffffu, zA0, off);
            zA1 += __shfl_xor_sync(0xffffffffu, zA1, off);
            zA2 += __shfl_xor_sync(0xffffffffu, zA2, off);
            zB0 += __shfl_xor_sync(0xffffffffu, zB0, off);
            zB1 += __shfl_xor_sync(0xffffffffu, zB1, off);
            zB2 += __shfl_xor_sync(0xffffffffu, zB2, off);
        }
        if ((lane & 3) == 0) {
            int colbase = (k < 5) ? 3 * k : 15 + 2 * (k - 5);
            int ncol = (k < 5) ? 3 : 2;
            int rowA = n0 + w * 16 + gr, rowB = rowA + 8;
            if (rowA < NN) {
                float di = g_dinv[rowA];
                float* zp = &g_Z[(size_t)rowA * ZC + colbase];
                float* pp = &g_P[(size_t)rowA * ZC + colbase];
                zp[0] = zA0 * di; zp[1] = zA1 * di;
                pp[0] = zA0 * di; pp[1] = zA1 * di;
                if (ncol == 3) { zp[2] = zA2 * di; pp[2] = zA2 * di; }
                if (k == 6) { g_Z[(size_t)rowA * ZC + 19] = 0.f; g_P[(size_t)rowA * ZC + 19] = 0.f; }
            }
            if (rowB < NN) {
                float di = g_dinv[rowB];
                float* zp = &g_Z[(size_t)rowB * ZC + colbase];
                float* pp = &g_P[(size_t)rowB * ZC + colbase];
                zp[0] = zB0 * di; zp[1] = zB1 * di;
                pp[0] = zB0 * di; pp[1] = zB1 * di;
                if (ncol == 3) { zp[2] = zB2 * di; pp[2] = zB2 * di; }
                if (k == 6) { g_Z[(size_t)rowB * ZC + 19] = 0.f; g_P[(size_t)rowB * ZC + 19] = 0.f; }
            }
        }
    }
}

// ================= tail =================
// P[d] += Z'[s]  (no weights; dinv[d] factored out into softmax)
__global__ void k_agg_z(const int* __restrict__ ei) {
    int e = blockIdx.x * blockDim.x + threadIdx.x;
    if (e >= NE) return;
    int s = ei[e];
    int d = ei[NE + e];
    const float4* zs = (const float4*)&g_Z[s * ZC];
    float* pd = &g_P[d * ZC];
    float4 v0 = zs[0], v1 = zs[1], v2 = zs[2], v3 = zs[3], v4 = zs[4];
    red_add_v4(pd + 0,  v0.x, v0.y, v0.z, v0.w);
    red_add_v4(pd + 4,  v1.x, v1.y, v1.z, v1.w);
    red_add_v4(pd + 8,  v2.x, v2.y, v2.z, v2.w);
    red_add_v4(pd + 12, v3.x, v3.y, v3.z, v3.w);
    red_add_v4(pd + 16, v4.x, v4.y, v4.z, v4.w);
}

__global__ void k_softmax(float* __restrict__ out) {
    int n = blockIdx.x * blockDim.x + threadIdx.x;
    if (n >= NN) return;
    float di = g_dinv[n];
    float p[20];
    const float4* pr = (const float4*)&g_P[n * ZC];
    #pragma unroll
    for (int ch = 0; ch < 5; ch++) {
        float4 v = pr[ch];
        float4 c = ((const float4*)g_c)[ch];
        p[ch * 4]     = fmaf(v.x, di, c.x);
        p[ch * 4 + 1] = fmaf(v.y, di, c.y);
        p[ch * 4 + 2] = fmaf(v.z, di, c.z);
        p[ch * 4 + 3] = fmaf(v.w, di, c.w);
    }
    #pragma unroll
    for (int k = 0; k < 5; k++) {
        float a = p[3 * k], b = p[3 * k + 1], c = p[3 * k + 2];
        float m = fmaxf(a, fmaxf(b, c));
        float ea = __expf(a - m), eb = __expf(b - m), ec = __expf(c - m);
        float inv = 1.f / (ea + eb + ec);
        long base = (long)(3 * k) * NN + (long)n * 3;
        out[base] = ea * inv; out[base + 1] = eb * inv; out[base + 2] = ec * inv;
    }
    #pragma unroll
    for (int k = 0; k < 2; k++) {
        float a = p[15 + 2 * k], b = p[15 + 2 * k + 1];
        float m = fmaxf(a, b);
        float ea = __expf(a - m), eb = __expf(b - m);
        float inv = 1.f / (ea + eb);
        long base = (long)(15 + 2 * k) * NN + (long)n * 2;
        out[base] = ea * inv; out[base + 1] = eb * inv;
    }
}

extern "C" void kernel_launch(void* const* d_in, const int* in_sizes, int n_in,
                              void* d_out, int out_size) {
    const float* x   = (const float*)d_in[0];
    const int*   ei  = (const int*)d_in[1];
    const float* gw_ = (const float*)d_in[2];
    const float* gb  = (const float*)d_in[3];
    const float* r3w = (const float*)d_in[4];
    const float* r3b = (const float*)d_in[5];
    const float* r2w = (const float*)d_in[6];
    const float* r2b = (const float*)d_in[7];
    float* out = (float*)d_out;

    const int SMEM = 4 * 128 * PITCH * 2 + 7 * HH * 16;   // 153600
    static int once = 0;
    if (!once) {
        cudaFuncSetAttribute(k_branch, cudaFuncAttributeMaxDynamicSharedMemorySize, SMEM);
        once = 1;
    }

    k_init_deg<<<(NN + 255) / 256, 256>>>();
    k_deg<<<(NE / 4 + 255) / 256, 256>>>((const int4*)(ei + NE));
    k_dinv<<<(NN + 255) / 256, 256>>>();
    k_y_init<<<(NN * 32 + 255) / 256, 256>>>((const float4*)x);
    k_mc<<<(19 * HH + 127) / 128, 128>>>(gw_, gb, r3w, r3b, r2w, r2b);
    k_prep_w<<<(7 * 128 * 64 + 127) / 128, 128>>>(gw_);
    k_prep_bm<<<(7 * HH + 127) / 128, 128>>>(gb);
    k_agg_y<<<(NE / 4 * 32 + 255) / 256, 256>>>((const float4*)x, ei);
    k_branch<<<NB, 256, SMEM>>>();
    k_agg_z<<<(NE + 255) / 256, 256>>>(ei);
    k_softmax<<<(NN + 255) / 256, 256>>>(out);
}

// round 8
// speedup vs baseline: 2.9466x; 1.1441x over previous
#include <cuda_runtime.h>
#include <cuda_fp16.h>
#include <cstdint>

#define NN 100000
#define NE 1600000
#define HH 128
#define ZC 20
#define NB 782            // ceil(NN/128)
#define PITCH 136         // smem row pitch in halves
#define TILE_GB 32768     // 128x128 fp16 tile bytes
#define SCAN_BLK 1024
#define NSCAN 98          // ceil(NN/1024)

// ---- scratch (device globals: allocation-free) ----
__device__ __align__(16) float g_dinv[NN];
__device__ __align__(16) float g_y[NN * HH];
__device__ __align__(16) float g_Z[NN * ZC];               // Z' = readout * dinv
__device__ __align__(16) float g_M[HH * ZC];
__device__ __align__(16) float g_c[ZC];
__device__ __align__(16) unsigned char g_Wh[7 * TILE_GB];
__device__ __align__(16) unsigned char g_Wl[7 * TILE_GB];
__device__ __align__(16) float g_BM[7 * HH * 4];
// CSR (in-edges grouped by dst)
__device__ __align__(16) int g_cnt[NN];
__device__ __align__(16) int g_fill[NN];
__device__ __align__(16) int g_row[NN + 1];
__device__ __align__(16) int g_srcl[NE];
__device__ int g_bsum[NSCAN];

__device__ __forceinline__ uint32_t smem_u32(const void* p) {
    uint32_t a;
    asm("{ .reg .u64 t; cvta.to.shared.u64 t, %1; cvt.u32.u64 %0, t; }" : "=r"(a) : "l"(p));
    return a;
}

// ================= CSR build =================
__global__ void k_init() {
    int i = blockIdx.x * blockDim.x + threadIdx.x;
    if (i < NN) { g_cnt[i] = 0; g_fill[i] = 0; }
}
__global__ void k_count(const int4* __restrict__ dst4) {
    int t = blockIdx.x * blockDim.x + threadIdx.x;
    if (t >= NE / 4) return;
    int4 d = dst4[t];
    atomicAdd(&g_cnt[d.x], 1);
    atomicAdd(&g_cnt[d.y], 1);
    atomicAdd(&g_cnt[d.z], 1);
    atomicAdd(&g_cnt[d.w], 1);
}
__global__ void k_dinv() {
    int i = blockIdx.x * blockDim.x + threadIdx.x;
    if (i < NN) g_dinv[i] = rsqrtf((float)g_cnt[i] + 1.0f);
}
__global__ void k_scan1() {
    __shared__ int sd[SCAN_BLK];
    int tid = threadIdx.x, i = blockIdx.x * SCAN_BLK + tid;
    int v = (i < NN) ? g_cnt[i] : 0;
    sd[tid] = v;
    __syncthreads();
    for (int off = 1; off < SCAN_BLK; off <<= 1) {
        int t = (tid >= off) ? sd[tid - off] : 0;
        __syncthreads();
        sd[tid] += t;
        __syncthreads();
    }
    if (i < NN) g_row[i] = sd[tid] - v;   // exclusive
    if (tid == SCAN_BLK - 1) g_bsum[blockIdx.x] = sd[tid];
}
__global__ void k_scan2() {
    if (threadIdx.x == 0) {
        int run = 0;
        for (int i = 0; i < NSCAN; i++) { int t = g_bsum[i]; g_bsum[i] = run; run += t; }
    }
}
__global__ void k_scan3() {
    int i = blockIdx.x * blockDim.x + threadIdx.x;
    if (i < NN) g_row[i] += g_bsum[i >> 10];
    if (i == 0) g_row[NN] = NE;
}
__global__ void k_scatter(const int* __restrict__ ei) {
    int e = blockIdx.x * blockDim.x + threadIdx.x;
    if (e >= NE) return;
    int s = ei[e];
    int d = ei[NE + e];
    int pos = g_row[d] + atomicAdd(&g_fill[d], 1);
    g_srcl[pos] = s;
}

// ================= y = A_hat x (CSR gather, warp per node) =================
__global__ void k_agg_y_csr(const float4* __restrict__ x4) {
    int n = (blockIdx.x * blockDim.x + threadIdx.x) >> 5;
    int lane = threadIdx.x & 31;
    if (n >= NN) return;
    int e = g_row[n], end = g_row[n + 1];
    float4 acc = make_float4(0.f, 0.f, 0.f, 0.f);
    for (; e + 1 < end; e += 2) {
        int s0 = g_srcl[e], s1 = g_srcl[e + 1];
        float w0 = g_dinv[s0], w1 = g_dinv[s1];
        float4 v0 = x4[s0 * 32 + lane];
        float4 v1 = x4[s1 * 32 + lane];
        acc.x += w0 * v0.x + w1 * v1.x;
        acc.y += w0 * v0.y + w1 * v1.y;
        acc.z += w0 * v0.z + w1 * v1.z;
        acc.w += w0 * v0.w + w1 * v1.w;
    }
    if (e < end) {
        int s0 = g_srcl[e];
        float w0 = g_dinv[s0];
        float4 v0 = x4[s0 * 32 + lane];
        acc.x += w0 * v0.x; acc.y += w0 * v0.y;
        acc.z += w0 * v0.z; acc.w += w0 * v0.w;
    }
    float di = g_dinv[n], invd = di * di;
    float4 xv = x4[n * 32 + lane];
    float4 y;
    y.x = di * acc.x + invd * xv.x;
    y.y = di * acc.y + invd * xv.y;
    y.z = di * acc.z + invd * xv.z;
    y.w = di * acc.w + invd * xv.w;
    ((float4*)g_y)[n * 32 + lane] = y;
}

// ================= weight prep =================
__global__ void k_mc(const float* __restrict__ gw_, const float* __restrict__ gb,
                     const float* __restrict__ r3w, const float* __restrict__ r3b,
                     const float* __restrict__ r2w, const float* __restrict__ r2b) {
    int t = blockIdx.x * blockDim.x + threadIdx.x;
    if (t >= 19 * HH) return;
    int col = t / HH, h = t % HH;
    int k; const float* R; float rb;
    if (col < 15) { k = col / 3; int c = col % 3; R = r3w + (k * 3 + c) * HH; rb = r3b[k * 3 + c]; }
    else { int cc = col - 15; k = 5 + cc / 2; int c = cc % 2; R = r2w + ((k - 5) * 2 + c) * HH; rb = r2b[(k - 5) * 2 + c]; }
    const float* Wrow = gw_ + k * HH * HH + h * HH;
    float acc = 0.f;
    #pragma unroll 8
    for (int j = 0; j < HH; j++) acc = fmaf(Wrow[j], R[j], acc);
    g_M[h * ZC + col] = acc;
    if (h == 0) {
        const float* b = gb + k * HH;
        float cb = 0.f;
        #pragma unroll 8
        for (int j = 0; j < HH; j++) cb = fmaf(b[j], R[j], cb);
        g_c[col] = cb + rb;
    }
    if (t == 0) g_c[19] = 0.f;
}

__global__ void k_prep_w(const float* __restrict__ gw_) {
    int t = blockIdx.x * blockDim.x + threadIdx.x;
    if (t >= 7 * 128 * 64) return;
    int k = t / 8192, r = t % 8192, f = r / 64, h = (r % 64) * 2;
    float w0 = gw_[k * 16384 + h * 128 + f];
    float w1 = gw_[k * 16384 + (h + 1) * 128 + f];
    __half h0 = __float2half_rn(w0), h1 = __float2half_rn(w1);
    __half l0 = __float2half_rn(w0 - __half2float(h0));
    __half l1 = __float2half_rn(w1 - __half2float(h1));
    int off = f * 256 + h * 2;
    *(uint32_t*)(g_Wh + k * TILE_GB + off) =
        ((uint32_t)__half_as_ushort(h1) << 16) | __half_as_ushort(h0);
    *(uint32_t*)(g_Wl + k * TILE_GB + off) =
        ((uint32_t)__half_as_ushort(l1) << 16) | __half_as_ushort(l0);
}

__global__ void k_prep_bm(const float* __restrict__ gb) {
    int t = blockIdx.x * blockDim.x + threadIdx.x;
    if (t >= 7 * HH) return;
    int k = t >> 7, f = t & 127;
    int colbase = (k < 5) ? 3 * k : 15 + 2 * (k - 5);
    int ncol = (k < 5) ? 3 : 2;
    float4 v;
    v.x = gb[k * HH + f];
    v.y = g_M[f * ZC + colbase];
    v.z = g_M[f * ZC + colbase + 1];
    v.w = (ncol == 3) ? g_M[f * ZC + colbase + 2] : 0.f;
    ((float4*)g_BM)[t] = v;
}

// ================= HMMA branch kernel =================
__global__ void __launch_bounds__(256) k_branch() {
    extern __shared__ __align__(16) unsigned char sm[];
    const int A_HI = 0;
    const int A_LO = A_HI + 128 * PITCH * 2;
    const int B_HI = A_LO + 128 * PITCH * 2;
    const int B_LO = B_HI + 128 * PITCH * 2;
    const int BM_OFF = B_LO + 128 * PITCH * 2;
    uint32_t sb = smem_u32(sm);
    int tid = threadIdx.x;
    int w = tid >> 5, lane = tid & 31;
    int n0 = blockIdx.x * 128;

    for (int idx = tid; idx < 128 * 64; idx += 256) {
        int row = idx >> 6, col = (idx & 63) * 2;
        float v0 = 0.f, v1 = 0.f;
        if (n0 + row < NN) {
            float2 p = *(const float2*)&g_y[(size_t)(n0 + row) * HH + col];
            v0 = p.x; v1 = p.y;
        }
        __half h0 = __float2half_rn(v0), h1 = __float2half_rn(v1);
        __half l0 = __float2half_rn(v0 - __half2float(h0));
        __half l1 = __float2half_rn(v1 - __half2float(h1));
        int off = row * (PITCH * 2) + col * 2;
        *(uint32_t*)(sm + A_HI + off) = ((uint32_t)__half_as_ushort(h1) << 16) | __half_as_ushort(h0);
        *(uint32_t*)(sm + A_LO + off) = ((uint32_t)__half_as_ushort(l1) << 16) | __half_as_ushort(l0);
    }
    {
        const uint4* src = (const uint4*)g_BM;
        uint4* dst = (uint4*)(sm + BM_OFF);
        for (int i = tid; i < 7 * HH; i += 256) dst[i] = src[i];
    }

    int a_row = lane & 15, a_cb = (lane >> 4) * 8;
    int b_row = ((lane >> 4) * 8) + (lane & 7);
    int b_kb = ((lane >> 3) & 1) * 8;
    const float4* bmt = (const float4*)(sm + BM_OFF);

    for (int k = 0; k < 7; k++) {
        __syncthreads();
        {
            const uint4* sh = (const uint4*)(g_Wh + k * TILE_GB);
            const uint4* sl = (const uint4*)(g_Wl + k * TILE_GB);
            for (int i = tid; i < 2048; i += 256) {
                int f = i >> 4, seg = i & 15;
                int off = f * (PITCH * 2) + seg * 16;
                *(uint4*)(sm + B_HI + off) = sh[i];
                *(uint4*)(sm + B_LO + off) = sl[i];
            }
        }
        __syncthreads();

        float acc[16][4];
        #pragma unroll
        for (int t = 0; t < 16; t++)
            #pragma unroll
            for (int j = 0; j < 4; j++) acc[t][j] = 0.f;

        #pragma unroll
        for (int pass = 0; pass < 3; pass++) {
            uint32_t Ab = sb + ((pass == 2) ? A_LO : A_HI);
            uint32_t Bb = sb + ((pass == 1) ? B_LO : B_HI);
            #pragma unroll
            for (int ks = 0; ks < 8; ks++) {
                uint32_t a0, a1, a2, a3;
                uint32_t aaddr = Ab + (w * 16 + a_row) * (PITCH * 2) + (ks * 16 + a_cb) * 2;
                asm volatile("ldmatrix.sync.aligned.m8n8.x4.shared.b16 {%0,%1,%2,%3}, [%4];"
                             : "=r"(a0), "=r"(a1), "=r"(a2), "=r"(a3) : "r"(aaddr));
                #pragma unroll
                for (int p = 0; p < 8; p++) {
                    uint32_t b0, b1, b2, b3;
                    uint32_t baddr = Bb + (p * 16 + b_row) * (PITCH * 2) + (ks * 16 + b_kb) * 2;
                    asm volatile("ldmatrix.sync.aligned.m8n8.x4.shared.b16 {%0,%1,%2,%3}, [%4];"
                                 : "=r"(b0), "=r"(b1), "=r"(b2), "=r"(b3) : "r"(baddr));
                    asm volatile(
                        "mma.sync.aligned.m16n8k16.row.col.f32.f16.f16.f32 "
                        "{%0,%1,%2,%3}, {%4,%5,%6,%7}, {%8,%9}, {%0,%1,%2,%3};"
                        : "+f"(acc[2*p][0]), "+f"(acc[2*p][1]), "+f"(acc[2*p][2]), "+f"(acc[2*p][3])
                        : "r"(a0), "r"(a1), "r"(a2), "r"(a3), "r"(b0), "r"(b1));
                    asm volatile(
                        "mma.sync.aligned.m16n8k16.row.col.f32.f16.f16.f32 "
                        "{%0,%1,%2,%3}, {%4,%5,%6,%7}, {%8,%9}, {%0,%1,%2,%3};"
                        : "+f"(acc[2*p+1][0]), "+f"(acc[2*p+1][1]), "+f"(acc[2*p+1][2]), "+f"(acc[2*p+1][3])
                        : "r"(a0), "r"(a1), "r"(a2), "r"(a3), "r"(b2), "r"(b3));
                }
            }
        }

        int gr = lane >> 2, cq = (lane & 3) * 2;
        float zA0 = 0.f, zA1 = 0.f, zA2 = 0.f, zB0 = 0.f, zB1 = 0.f, zB2 = 0.f;
        #pragma unroll
        for (int nt = 0; nt < 16; nt++) {
            float4 m0 = bmt[k * HH + nt * 8 + cq];
            float4 m1 = bmt[k * HH + nt * 8 + cq + 1];
            float hA0 = fmaxf(acc[nt][0] + m0.x, 0.f);
            float hA1 = fmaxf(acc[nt][1] + m1.x, 0.f);
            float hB0 = fmaxf(acc[nt][2] + m0.x, 0.f);
            float hB1 = fmaxf(acc[nt][3] + m1.x, 0.f);
            zA0 = fmaf(hA0, m0.y, fmaf(hA1, m1.y, zA0));
            zA1 = fmaf(hA0, m0.z, fmaf(hA1, m1.z, zA1));
            zA2 = fmaf(hA0, m0.w, fmaf(hA1, m1.w, zA2));
            zB0 = fmaf(hB0, m0.y, fmaf(hB1, m1.y, zB0));
            zB1 = fmaf(hB0, m0.z, fmaf(hB1, m1.z, zB1));
            zB2 = fmaf(hB0, m0.w, fmaf(hB1, m1.w, zB2));
        }
        #pragma unroll
        for (int off = 1; off < 4; off <<= 1) {
            zA0 += __shfl_xor_sync(0xffffffffu, zA0, off);
            zA1 += __shfl_xor_sync(0xffffffffu, zA1, off);
            zA2 += __shfl_xor_sync(0xffffffffu, zA2, off);
            zB0 += __shfl_xor_sync(0xffffffffu, zB0, off);
            zB1 += __shfl_xor_sync(0xffffffffu, zB1, off);
            zB2 += __shfl_xor_sync(0xffffffffu, zB2, off);
        }
        if ((lane & 3) == 0) {
            int colbase = (k < 5) ? 3 * k : 15 + 2 * (k - 5);
            int ncol = (k < 5) ? 3 : 2;
            int rowA = n0 + w * 16 + gr, rowB = rowA + 8;
            if (rowA < NN) {
                float di = g_dinv[rowA];
                float* zp = &g_Z[(size_t)rowA * ZC + colbase];
                zp[0] = zA0 * di; zp[1] = zA1 * di;
                if (ncol == 3) zp[2] = zA2 * di;
            }
            if (rowB < NN) {
                float di = g_dinv[rowB];
                float* zp = &g_Z[(size_t)rowB * ZC + colbase];
                zp[0] = zB0 * di; zp[1] = zB1 * di;
                if (ncol == 3) zp[2] = zB2 * di;
            }
        }
    }
}

// ================= fused CSR-aggregate + softmax (warp per node) =================
__global__ void k_softmax_fused(float* __restrict__ out) {
    int n = (blockIdx.x * blockDim.x + threadIdx.x) >> 5;
    int lane = threadIdx.x & 31;
    if (n >= NN) return;
    bool active = lane < 19;
    float acc = active ? g_Z[(size_t)n * ZC + lane] : 0.f;  // self term Z'[n]
    int e = g_row[n], end = g_row[n + 1];
    for (; e + 1 < end; e += 2) {
        int s0 = g_srcl[e], s1 = g_srcl[e + 1];
        float v0 = active ? g_Z[(size_t)s0 * ZC + lane] : 0.f;
        float v1 = active ? g_Z[(size_t)s1 * ZC + lane] : 0.f;
        acc += v0 + v1;
    }
    if (e < end) {
        int s0 = g_srcl[e];
        acc += active ? g_Z[(size_t)s0 * ZC + lane] : 0.f;
    }
    float di = g_dinv[n];
    float p = active ? fmaf(acc, di, g_c[lane]) : -1e30f;

    int base, ncol, j;
    if (lane < 15) { base = lane - (lane % 3); ncol = 3; j = lane - base; }
    else { base = 15 + ((lane - 15) & ~1); ncol = 2; j = lane - base; }
    float v0 = __shfl_sync(0xffffffffu, p, base);
    float v1 = __shfl_sync(0xffffffffu, p, base + 1);
    float v2 = (ncol == 3) ? __shfl_sync(0xffffffffu, p, base + 2) : -1e30f;
    float m = fmaxf(v0, fmaxf(v1, v2));
    float sum = __expf(v0 - m) + __expf(v1 - m) + ((ncol == 3) ? __expf(v2 - m) : 0.f);
    float mine = __expf(p - m) / sum;
    if (active)
        out[(long)base * NN + (long)n * ncol + j] = mine;
}

extern "C" void kernel_launch(void* const* d_in, const int* in_sizes, int n_in,
                              void* d_out, int out_size) {
    const float* x   = (const float*)d_in[0];
    const int*   ei  = (const int*)d_in[1];
    const float* gw_ = (const float*)d_in[2];
    const float* gb  = (const float*)d_in[3];
    const float* r3w = (const float*)d_in[4];
    const float* r3b = (const float*)d_in[5];
    const float* r2w = (const float*)d_in[6];
    const float* r2b = (const float*)d_in[7];
    float* out = (float*)d_out;

    const int SMEM = 4 * 128 * PITCH * 2 + 7 * HH * 16;
    static int once = 0;
    if (!once) {
        cudaFuncSetAttribute(k_branch, cudaFuncAttributeMaxDynamicSharedMemorySize, SMEM);
        once = 1;
    }

    // CSR build
    k_init<<<(NN + 255) / 256, 256>>>();
    k_count<<<(NE / 4 + 255) / 256, 256>>>((const int4*)(ei + NE));
    k_dinv<<<(NN + 255) / 256, 256>>>();
    k_scan1<<<NSCAN, SCAN_BLK>>>();
    k_scan2<<<1, 32>>>();
    k_scan3<<<(NN + 255) / 256, 256>>>();
    k_scatter<<<(NE + 255) / 256, 256>>>(ei);
    // weight prep (independent)
    k_mc<<<(19 * HH + 127) / 128, 128>>>(gw_, gb, r3w, r3b, r2w, r2b);
    k_prep_w<<<(7 * 128 * 64 + 127) / 128, 128>>>(gw_);
    k_prep_bm<<<(7 * HH + 127) / 128, 128>>>(gb);
    // main pipeline
    k_agg_y_csr<<<(NN * 32 + 255) / 256, 256>>>((const float4*)x);
    k_branch<<<NB, 256, SMEM>>>();
    k_softmax_fused<<<(NN * 32 + 255) / 256, 256>>>(out);
}

// round 9
// speedup vs baseline: 4.2529x; 1.4433x over previous
#include <cuda_runtime.h>
#include <cuda_fp16.h>
#include <cstdint>

#define NN 100000
#define NE 1600000
#define HH 128
#define ZC 20
#define NB 782            // ceil(NN/128)
#define PITCH 136         // smem row pitch in halves
#define TILE_GB 32768     // 128x128 fp16 tile bytes
#define SCAN_BLK 1024
#define NSCAN 98          // ceil(NN/1024)

// ---- scratch (device globals: allocation-free) ----
__device__ __align__(16) float g_dinv[NN];
__device__ __align__(16) uint32_t g_yh[NN * 64];           // y as half2 pairs [n][64]
__device__ __align__(16) float g_Z[NN * ZC];               // Z' = readout * dinv
__device__ __align__(16) float g_M[HH * ZC];
__device__ __align__(16) float g_c[ZC];
__device__ __align__(16) unsigned char g_Wh[7 * TILE_GB];
__device__ __align__(16) unsigned char g_Wl[7 * TILE_GB];
__device__ __align__(16) float g_BM[7 * HH * 4];
// CSR (in-edges grouped by dst); row becomes END cursor after scatter
__device__ __align__(16) int g_cnt[NN];
__device__ __align__(16) int g_row[NN];
__device__ __align__(16) int g_srcl[NE];
__device__ int g_bsum[NSCAN];

__device__ __forceinline__ uint32_t smem_u32(const void* p) {
    uint32_t a;
    asm("{ .reg .u64 t; cvta.to.shared.u64 t, %1; cvt.u32.u64 %0, t; }" : "=r"(a) : "l"(p));
    return a;
}

// ================= CSR build =================
__global__ void k_init() {
    int i = blockIdx.x * blockDim.x + threadIdx.x;
    if (i < NN) g_cnt[i] = 0;
}
__global__ void k_count(const int4* __restrict__ dst4) {
    int t = blockIdx.x * blockDim.x + threadIdx.x;
    if (t >= NE / 4) return;
    int4 d = dst4[t];
    atomicAdd(&g_cnt[d.x], 1);
    atomicAdd(&g_cnt[d.y], 1);
    atomicAdd(&g_cnt[d.z], 1);
    atomicAdd(&g_cnt[d.w], 1);
}
__global__ void k_dinv() {
    int i = blockIdx.x * blockDim.x + threadIdx.x;
    if (i < NN) g_dinv[i] = rsqrtf((float)g_cnt[i] + 1.0f);
}
__global__ void k_scan1() {
    __shared__ int sd[SCAN_BLK];
    int tid = threadIdx.x, i = blockIdx.x * SCAN_BLK + tid;
    int v = (i < NN) ? g_cnt[i] : 0;
    sd[tid] = v;
    __syncthreads();
    for (int off = 1; off < SCAN_BLK; off <<= 1) {
        int t = (tid >= off) ? sd[tid - off] : 0;
        __syncthreads();
        sd[tid] += t;
        __syncthreads();
    }
    if (i < NN) g_row[i] = sd[tid] - v;   // exclusive start
    if (tid == SCAN_BLK - 1) g_bsum[blockIdx.x] = sd[tid];
}
__global__ void k_scan2() {
    if (threadIdx.x == 0) {
        int run = 0;
        for (int i = 0; i < NSCAN; i++) { int t = g_bsum[i]; g_bsum[i] = run; run += t; }
    }
}
__global__ void k_scan3() {
    int i = blockIdx.x * blockDim.x + threadIdx.x;
    if (i < NN) g_row[i] += g_bsum[i >> 10];
}
// scatter bumps row cursor; afterwards row[d] = end, start = end - cnt
__global__ void k_scatter(const int* __restrict__ ei) {
    int e = blockIdx.x * blockDim.x + threadIdx.x;
    if (e >= NE) return;
    int s = ei[e];
    int d = ei[NE + e];
    int pos = atomicAdd(&g_row[d], 1);
    g_srcl[pos] = s;
}

// ================= y = A_hat x (CSR gather, warp per node, fp16 out) =========
__global__ void k_agg_y_csr(const float4* __restrict__ x4) {
    int n = (blockIdx.x * blockDim.x + threadIdx.x) >> 5;
    int lane = threadIdx.x & 31;
    if (n >= NN) return;
    int end = g_row[n], e = end - g_cnt[n];
    float4 acc = make_float4(0.f, 0.f, 0.f, 0.f);
    for (; e + 1 < end; e += 2) {
        int s0 = g_srcl[e], s1 = g_srcl[e + 1];
        float w0 = g_dinv[s0], w1 = g_dinv[s1];
        float4 v0 = x4[s0 * 32 + lane];
        float4 v1 = x4[s1 * 32 + lane];
        acc.x += w0 * v0.x + w1 * v1.x;
        acc.y += w0 * v0.y + w1 * v1.y;
        acc.z += w0 * v0.z + w1 * v1.z;
        acc.w += w0 * v0.w + w1 * v1.w;
    }
    if (e < end) {
        int s0 = g_srcl[e];
        float w0 = g_dinv[s0];
        float4 v0 = x4[s0 * 32 + lane];
        acc.x += w0 * v0.x; acc.y += w0 * v0.y;
        acc.z += w0 * v0.z; acc.w += w0 * v0.w;
    }
    float di = g_dinv[n], invd = di * di;
    float4 xv = x4[n * 32 + lane];
    float y0 = di * acc.x + invd * xv.x;
    float y1 = di * acc.y + invd * xv.y;
    float y2 = di * acc.z + invd * xv.z;
    float y3 = di * acc.w + invd * xv.w;
    __half2 p0 = __floats2half2_rn(y0, y1);
    __half2 p1 = __floats2half2_rn(y2, y3);
    uint2 w;
    w.x = *(uint32_t*)&p0;
    w.y = *(uint32_t*)&p1;
    *(uint2*)&g_yh[n * 64 + lane * 2] = w;
}

// ================= weight prep =================
__global__ void k_mc(const float* __restrict__ gw_, const float* __restrict__ gb,
                     const float* __restrict__ r3w, const float* __restrict__ r3b,
                     const float* __restrict__ r2w, const float* __restrict__ r2b) {
    int t = blockIdx.x * blockDim.x + threadIdx.x;
    if (t >= 19 * HH) return;
    int col = t / HH, h = t % HH;
    int k; const float* R; float rb;
    if (col < 15) { k = col / 3; int c = col % 3; R = r3w + (k * 3 + c) * HH; rb = r3b[k * 3 + c]; }
    else { int cc = col - 15; k = 5 + cc / 2; int c = cc % 2; R = r2w + ((k - 5) * 2 + c) * HH; rb = r2b[(k - 5) * 2 + c]; }
    const float* Wrow = gw_ + k * HH * HH + h * HH;
    float acc = 0.f;
    #pragma unroll 8
    for (int j = 0; j < HH; j++) acc = fmaf(Wrow[j], R[j], acc);
    g_M[h * ZC + col] = acc;
    if (h == 0) {
        const float* b = gb + k * HH;
        float cb = 0.f;
        #pragma unroll 8
        for (int j = 0; j < HH; j++) cb = fmaf(b[j], R[j], cb);
        g_c[col] = cb + rb;
    }
    if (t == 0) g_c[19] = 0.f;
}

__global__ void k_prep_w(const float* __restrict__ gw_) {
    int t = blockIdx.x * blockDim.x + threadIdx.x;
    if (t >= 7 * 128 * 64) return;
    int k = t / 8192, r = t % 8192, f = r / 64, h = (r % 64) * 2;
    float w0 = gw_[k * 16384 + h * 128 + f];
    float w1 = gw_[k * 16384 + (h + 1) * 128 + f];
    __half h0 = __float2half_rn(w0), h1 = __float2half_rn(w1);
    __half l0 = __float2half_rn(w0 - __half2float(h0));
    __half l1 = __float2half_rn(w1 - __half2float(h1));
    int off = f * 256 + h * 2;
    *(uint32_t*)(g_Wh + k * TILE_GB + off) =
        ((uint32_t)__half_as_ushort(h1) << 16) | __half_as_ushort(h0);
    *(uint32_t*)(g_Wl + k * TILE_GB + off) =
        ((uint32_t)__half_as_ushort(l1) << 16) | __half_as_ushort(l0);
}

__global__ void k_prep_bm(const float* __restrict__ gb) {
    int t = blockIdx.x * blockDim.x + threadIdx.x;
    if (t >= 7 * HH) return;
    int k = t >> 7, f = t & 127;
    int colbase = (k < 5) ? 3 * k : 15 + 2 * (k - 5);
    int ncol = (k < 5) ? 3 : 2;
    float4 v;
    v.x = gb[k * HH + f];
    v.y = g_M[f * ZC + colbase];
    v.z = g_M[f * ZC + colbase + 1];
    v.w = (ncol == 3) ? g_M[f * ZC + colbase + 2] : 0.f;
    ((float4*)g_BM)[t] = v;
}

// ================= HMMA branch kernel (2-pass, 2 CTAs/SM) =================
__global__ void __launch_bounds__(256, 2) k_branch() {
    extern __shared__ __align__(16) unsigned char sm[];
    const int A_OFF = 0;
    const int B_HI = A_OFF + 128 * PITCH * 2;
    const int B_LO = B_HI + 128 * PITCH * 2;
    uint32_t sb = smem_u32(sm);
    int tid = threadIdx.x;
    int w = tid >> 5, lane = tid & 31;
    int n0 = blockIdx.x * 128;

    // copy y tile (already fp16) into padded smem
    for (int idx = tid; idx < 128 * 64; idx += 256) {
        int row = idx >> 6, c2 = idx & 63;
        uint32_t v = (n0 + row < NN) ? g_yh[(size_t)(n0 + row) * 64 + c2] : 0u;
        *(uint32_t*)(sm + A_OFF + row * (PITCH * 2) + c2 * 4) = v;
    }

    int a_row = lane & 15, a_cb = (lane >> 4) * 8;
    int b_row = ((lane >> 4) * 8) + (lane & 7);
    int b_kb = ((lane >> 3) & 1) * 8;
    const float4* bmt = (const float4*)g_BM;

    for (int k = 0; k < 7; k++) {
        __syncthreads();
        {
            const uint4* sh = (const uint4*)(g_Wh + k * TILE_GB);
            const uint4* sl = (const uint4*)(g_Wl + k * TILE_GB);
            for (int i = tid; i < 2048; i += 256) {
                int f = i >> 4, seg = i & 15;
                int off = f * (PITCH * 2) + seg * 16;
                *(uint4*)(sm + B_HI + off) = sh[i];
                *(uint4*)(sm + B_LO + off) = sl[i];
            }
        }
        __syncthreads();

        float acc[16][4];
        #pragma unroll
        for (int t = 0; t < 16; t++)
            #pragma unroll
            for (int j = 0; j < 4; j++) acc[t][j] = 0.f;

        #pragma unroll
        for (int pass = 0; pass < 2; pass++) {
            uint32_t Ab = sb + A_OFF;
            uint32_t Bb = sb + ((pass == 1) ? B_LO : B_HI);
            #pragma unroll
            for (int ks = 0; ks < 8; ks++) {
                uint32_t a0, a1, a2, a3;
                uint32_t aaddr = Ab + (w * 16 + a_row) * (PITCH * 2) + (ks * 16 + a_cb) * 2;
                asm volatile("ldmatrix.sync.aligned.m8n8.x4.shared.b16 {%0,%1,%2,%3}, [%4];"
                             : "=r"(a0), "=r"(a1), "=r"(a2), "=r"(a3) : "r"(aaddr));
                #pragma unroll
                for (int p = 0; p < 8; p++) {
                    uint32_t b0, b1, b2, b3;
                    uint32_t baddr = Bb + (p * 16 + b_row) * (PITCH * 2) + (ks * 16 + b_kb) * 2;
                    asm volatile("ldmatrix.sync.aligned.m8n8.x4.shared.b16 {%0,%1,%2,%3}, [%4];"
                                 : "=r"(b0), "=r"(b1), "=r"(b2), "=r"(b3) : "r"(baddr));
                    asm volatile(
                        "mma.sync.aligned.m16n8k16.row.col.f32.f16.f16.f32 "
                        "{%0,%1,%2,%3}, {%4,%5,%6,%7}, {%8,%9}, {%0,%1,%2,%3};"
                        : "+f"(acc[2*p][0]), "+f"(acc[2*p][1]), "+f"(acc[2*p][2]), "+f"(acc[2*p][3])
                        : "r"(a0), "r"(a1), "r"(a2), "r"(a3), "r"(b0), "r"(b1));
                    asm volatile(
                        "mma.sync.aligned.m16n8k16.row.col.f32.f16.f16.f32 "
                        "{%0,%1,%2,%3}, {%4,%5,%6,%7}, {%8,%9}, {%0,%1,%2,%3};"
                        : "+f"(acc[2*p+1][0]), "+f"(acc[2*p+1][1]), "+f"(acc[2*p+1][2]), "+f"(acc[2*p+1][3])
                        : "r"(a0), "r"(a1), "r"(a2), "r"(a3), "r"(b2), "r"(b3));
                }
            }
        }

        int gr = lane >> 2, cq = (lane & 3) * 2;
        float zA0 = 0.f, zA1 = 0.f, zA2 = 0.f, zB0 = 0.f, zB1 = 0.f, zB2 = 0.f;
        #pragma unroll
        for (int nt = 0; nt < 16; nt++) {
            float4 m0 = __ldg(&bmt[k * HH + nt * 8 + cq]);
            float4 m1 = __ldg(&bmt[k * HH + nt * 8 + cq + 1]);
            float hA0 = fmaxf(acc[nt][0] + m0.x, 0.f);
            float hA1 = fmaxf(acc[nt][1] + m1.x, 0.f);
            float hB0 = fmaxf(acc[nt][2] + m0.x, 0.f);
            float hB1 = fmaxf(acc[nt][3] + m1.x, 0.f);
            zA0 = fmaf(hA0, m0.y, fmaf(hA1, m1.y, zA0));
            zA1 = fmaf(hA0, m0.z, fmaf(hA1, m1.z, zA1));
            zA2 = fmaf(hA0, m0.w, fmaf(hA1, m1.w, zA2));
            zB0 = fmaf(hB0, m0.y, fmaf(hB1, m1.y, zB0));
            zB1 = fmaf(hB0, m0.z, fmaf(hB1, m1.z, zB1));
            zB2 = fmaf(hB0, m0.w, fmaf(hB1, m1.w, zB2));
        }
        #pragma unroll
        for (int off = 1; off < 4; off <<= 1) {
            zA0 += __shfl_xor_sync(0xffffffffu, zA0, off);
            zA1 += __shfl_xor_sync(0xffffffffu, zA1, off);
            zA2 += __shfl_xor_sync(0xffffffffu, zA2, off);
            zB0 += __shfl_xor_sync(0xffffffffu, zB0, off);
            zB1 += __shfl_xor_sync(0xffffffffu, zB1, off);
            zB2 += __shfl_xor_sync(0xffffffffu, zB2, off);
        }
        if ((lane & 3) == 0) {
            int colbase = (k < 5) ? 3 * k : 15 + 2 * (k - 5);
            int ncol = (k < 5) ? 3 : 2;
            int rowA = n0 + w * 16 + gr, rowB = rowA + 8;
            if (rowA < NN) {
                float di = g_dinv[rowA];
                float* zp = &g_Z[(size_t)rowA * ZC + colbase];
                zp[0] = zA0 * di; zp[1] = zA1 * di;
                if (ncol == 3) zp[2] = zA2 * di;
            }
            if (rowB < NN) {
                float di = g_dinv[rowB];
                float* zp = &g_Z[(size_t)rowB * ZC + colbase];
                zp[0] = zB0 * di; zp[1] = zB1 * di;
                if (ncol == 3) zp[2] = zB2 * di;
            }
        }
    }
}

// ================= fused CSR-aggregate + softmax (warp per node) =================
__global__ void k_softmax_fused(float* __restrict__ out) {
    int n = (blockIdx.x * blockDim.x + threadIdx.x) >> 5;
    int lane = threadIdx.x & 31;
    if (n >= NN) return;
    bool active = lane < 19;
    float acc = active ? g_Z[(size_t)n * ZC + lane] : 0.f;  // self term Z'[n]
    int end = g_row[n], e = end - g_cnt[n];
    for (; e + 1 < end; e += 2) {
        int s0 = g_srcl[e], s1 = g_srcl[e + 1];
        float v0 = active ? g_Z[(size_t)s0 * ZC + lane] : 0.f;
        float v1 = active ? g_Z[(size_t)s1 * ZC + lane] : 0.f;
        acc += v0 + v1;
    }
    if (e < end) {
        int s0 = g_srcl[e];
        acc += active ? g_Z[(size_t)s0 * ZC + lane] : 0.f;
    }
    float di = g_dinv[n];
    float p = active ? fmaf(acc, di, g_c[lane]) : -1e30f;

    int base, ncol, j;
    if (lane < 15) { base = lane - (lane % 3); ncol = 3; j = lane - base; }
    else { base = 15 + ((lane - 15) & ~1); ncol = 2; j = lane - base; }
    float v0 = __shfl_sync(0xffffffffu, p, base);
    float v1 = __shfl_sync(0xffffffffu, p, base + 1);
    float v2 = (ncol == 3) ? __shfl_sync(0xffffffffu, p, base + 2) : -1e30f;
    float m = fmaxf(v0, fmaxf(v1, v2));
    float sum = __expf(v0 - m) + __expf(v1 - m) + ((ncol == 3) ? __expf(v2 - m) : 0.f);
    float mine = __expf(p - m) / sum;
    if (active)
        out[(long)base * NN + (long)n * ncol + j] = mine;
}

extern "C" void kernel_launch(void* const* d_in, const int* in_sizes, int n_in,
                              void* d_out, int out_size) {
    const float* x   = (const float*)d_in[0];
    const int*   ei  = (const int*)d_in[1];
    const float* gw_ = (const float*)d_in[2];
    const float* gb  = (const float*)d_in[3];
    const float* r3w = (const float*)d_in[4];
    const float* r3b = (const float*)d_in[5];
    const float* r2w = (const float*)d_in[6];
    const float* r2b = (const float*)d_in[7];
    float* out = (float*)d_out;

    const int SMEM = 3 * 128 * PITCH * 2;   // 104448
    static int once = 0;
    if (!once) {
        cudaFuncSetAttribute(k_branch, cudaFuncAttributeMaxDynamicSharedMemorySize, SMEM);
        once = 1;
    }

    // CSR build
    k_init<<<(NN + 255) / 256, 256>>>();
    k_count<<<(NE / 4 + 255) / 256, 256>>>((const int4*)(ei + NE));
    k_dinv<<<(NN + 255) / 256, 256>>>();
    k_scan1<<<NSCAN, SCAN_BLK>>>();
    k_scan2<<<1, 32>>>();
    k_scan3<<<(NN + 255) / 256, 256>>>();
    k_scatter<<<(NE + 255) / 256, 256>>>(ei);
    // weight prep (independent)
    k_mc<<<(19 * HH + 127) / 128, 128>>>(gw_, gb, r3w, r3b, r2w, r2b);
    k_prep_w<<<(7 * 128 * 64 + 127) / 128, 128>>>(gw_);
    k_prep_bm<<<(7 * HH + 127) / 128, 128>>>(gb);
    // main pipeline
    k_agg_y_csr<<<(NN * 32 + 255) / 256, 256>>>((const float4*)x);
    k_branch<<<NB, 256, SMEM>>>();
    k_softmax_fused<<<(NN * 32 + 255) / 256, 256>>>(out);
}

// round 10
// speedup vs baseline: 5.4877x; 1.2904x over previous
#include <cuda_runtime.h>
#include <cuda_fp16.h>
#include <cstdint>

#define NN 100000
#define NE 1600000
#define HH 128
#define ZC 20
#define NB 782            // ceil(NN/128)
#define PITCH 136         // smem row pitch in halves
#define TILE_GB 32768     // 128x128 fp16 tile bytes
#define SCAN_BLK 1024
#define NSCAN 98          // ceil(NN/1024)

// ---- scratch (device globals: allocation-free) ----
__device__ __align__(16) float g_dinv[NN];
__device__ __align__(16) uint32_t g_xh[NN * 64];           // xs = x*dinv, half2 pairs
__device__ __align__(16) uint32_t g_yh[NN * 64];           // y,  half2 pairs
__device__ __align__(16) __half g_Zh[NN * ZC];             // Z' = readout * dinv (fp16)
__device__ __align__(16) float g_c[ZC];
__device__ __align__(16) unsigned char g_Wh[7 * TILE_GB];  // W^T fp16 [f][h]
__device__ __align__(16) float g_BM[7 * HH * 4];           // {bias, M0, M1, M2}
// CSR (in-edges grouped by dst); row becomes END cursor after scatter
__device__ __align__(16) int g_cnt[NN];
__device__ __align__(16) int g_row[NN];
__device__ __align__(16) int g_srcl[NE];
__device__ int g_bsum[NSCAN];

__device__ __forceinline__ uint32_t smem_u32(const void* p) {
    uint32_t a;
    asm("{ .reg .u64 t; cvta.to.shared.u64 t, %1; cvt.u32.u64 %0, t; }" : "=r"(a) : "l"(p));
    return a;
}

// ================= CSR build =================
__global__ void k_init() {
    int i = blockIdx.x * blockDim.x + threadIdx.x;
    if (i < NN) g_cnt[i] = 0;
}
__global__ void k_count(const int4* __restrict__ dst4) {
    int t = blockIdx.x * blockDim.x + threadIdx.x;
    if (t >= NE / 4) return;
    int4 d = dst4[t];
    atomicAdd(&g_cnt[d.x], 1);
    atomicAdd(&g_cnt[d.y], 1);
    atomicAdd(&g_cnt[d.z], 1);
    atomicAdd(&g_cnt[d.w], 1);
}
__global__ void k_scan1() {   // also computes dinv
    __shared__ int sd[SCAN_BLK];
    int tid = threadIdx.x, i = blockIdx.x * SCAN_BLK + tid;
    int v = (i < NN) ? g_cnt[i] : 0;
    if (i < NN) g_dinv[i] = rsqrtf((float)v + 1.0f);
    sd[tid] = v;
    __syncthreads();
    for (int off = 1; off < SCAN_BLK; off <<= 1) {
        int t = (tid >= off) ? sd[tid - off] : 0;
        __syncthreads();
        sd[tid] += t;
        __syncthreads();
    }
    if (i < NN) g_row[i] = sd[tid] - v;   // exclusive start
    if (tid == SCAN_BLK - 1) g_bsum[blockIdx.x] = sd[tid];
}
__global__ void k_scan2() {
    if (threadIdx.x == 0) {
        int run = 0;
        for (int i = 0; i < NSCAN; i++) { int t = g_bsum[i]; g_bsum[i] = run; run += t; }
    }
}
__global__ void k_scan3() {
    int i = blockIdx.x * blockDim.x + threadIdx.x;
    if (i < NN) g_row[i] += g_bsum[i >> 10];
}
__global__ void k_scatter(const int* __restrict__ ei) {
    int e = blockIdx.x * blockDim.x + threadIdx.x;
    if (e >= NE) return;
    int s = ei[e];
    int d = ei[NE + e];
    int pos = atomicAdd(&g_row[d], 1);
    g_srcl[pos] = s;
}

// ================= xs = x * dinv -> fp16 =================
__global__ void k_xh(const float4* __restrict__ x4) {
    int idx = blockIdx.x * blockDim.x + threadIdx.x;
    if (idx >= NN * 32) return;
    int n = idx >> 5;
    float di = g_dinv[n];
    float4 v = x4[idx];
    __half2 p0 = __floats2half2_rn(v.x * di, v.y * di);
    __half2 p1 = __floats2half2_rn(v.z * di, v.w * di);
    uint2 w;
    w.x = *(uint32_t*)&p0;
    w.y = *(uint32_t*)&p1;
    *(uint2*)&g_xh[(size_t)n * 64 + (idx & 31) * 2] = w;
}

// ================= y = A_hat x (CSR fp16 gather, warp per node) =============
__global__ void k_agg_y_csr() {
    int n = (blockIdx.x * blockDim.x + threadIdx.x) >> 5;
    int lane = threadIdx.x & 31;
    if (n >= NN) return;
    int end = g_row[n], e = end - g_cnt[n];
    const uint2* xh = (const uint2*)g_xh;
    // self term
    uint2 sv = xh[(size_t)n * 32 + lane];
    __half2 s0h = *(__half2*)&sv.x, s1h = *(__half2*)&sv.y;
    float2 f0 = __half22float2(s0h), f1 = __half22float2(s1h);
    float a0 = f0.x, a1 = f0.y, a2 = f1.x, a3 = f1.y;
    for (; e + 1 < end; e += 2) {
        int q0 = g_srcl[e], q1 = g_srcl[e + 1];
        uint2 v0 = xh[(size_t)q0 * 32 + lane];
        uint2 v1 = xh[(size_t)q1 * 32 + lane];
        float2 u0 = __half22float2(*(__half2*)&v0.x), u1 = __half22float2(*(__half2*)&v0.y);
        float2 u2 = __half22float2(*(__half2*)&v1.x), u3 = __half22float2(*(__half2*)&v1.y);
        a0 += u0.x + u2.x; a1 += u0.y + u2.y;
        a2 += u1.x + u3.x; a3 += u1.y + u3.y;
    }
    if (e < end) {
        int q0 = g_srcl[e];
        uint2 v0 = xh[(size_t)q0 * 32 + lane];
        float2 u0 = __half22float2(*(__half2*)&v0.x), u1 = __half22float2(*(__half2*)&v0.y);
        a0 += u0.x; a1 += u0.y; a2 += u1.x; a3 += u1.y;
    }
    float di = g_dinv[n];
    __half2 p0 = __floats2half2_rn(a0 * di, a1 * di);
    __half2 p1 = __floats2half2_rn(a2 * di, a3 * di);
    uint2 w;
    w.x = *(uint32_t*)&p0;
    w.y = *(uint32_t*)&p1;
    *(uint2*)&g_yh[(size_t)n * 64 + lane * 2] = w;
}

// ================= weight prep =================
// Fused: M = W_k R_k^T directly into BM table + c vector.
__global__ void k_mc(const float* __restrict__ gw_, const float* __restrict__ gb,
                     const float* __restrict__ r3w, const float* __restrict__ r3b,
                     const float* __restrict__ r2w, const float* __restrict__ r2b) {
    int t = blockIdx.x * blockDim.x + threadIdx.x;
    if (t >= 19 * HH) return;
    int col = t / HH, h = t % HH;
    int k; const float* R; float rb;
    if (col < 15) { k = col / 3; int c = col % 3; R = r3w + (k * 3 + c) * HH; rb = r3b[k * 3 + c]; }
    else { int cc = col - 15; k = 5 + cc / 2; int c = cc % 2; R = r2w + ((k - 5) * 2 + c) * HH; rb = r2b[(k - 5) * 2 + c]; }
    const float* Wrow = gw_ + k * HH * HH + h * HH;
    float acc = 0.f;
    #pragma unroll 8
    for (int j = 0; j < HH; j++) acc = fmaf(Wrow[j], R[j], acc);
    int colbase = (k < 5) ? 3 * k : 15 + 2 * (k - 5);
    g_BM[(k * HH + h) * 4 + 1 + (col - colbase)] = acc;
    // bias component + zero pad for 2-col branches
    if (t < 7 * HH) {
        int k2 = t >> 7, f = t & 127;
        g_BM[t * 4] = gb[k2 * HH + f];
        if (k2 >= 5) g_BM[t * 4 + 3] = 0.f;
    }
    if (h == 0) {
        const float* b = gb + k * HH;
        float cb = 0.f;
        #pragma unroll 8
        for (int j = 0; j < HH; j++) cb = fmaf(b[j], R[j], cb);
        g_c[col] = cb + rb;
    }
    if (t == 0) g_c[19] = 0.f;
}

__global__ void k_prep_w(const float* __restrict__ gw_) {
    int t = blockIdx.x * blockDim.x + threadIdx.x;
    if (t >= 7 * 128 * 64) return;
    int k = t / 8192, r = t % 8192, f = r / 64, h = (r % 64) * 2;
    float w0 = gw_[k * 16384 + h * 128 + f];
    float w1 = gw_[k * 16384 + (h + 1) * 128 + f];
    __half h0 = __float2half_rn(w0), h1 = __float2half_rn(w1);
    int off = f * 256 + h * 2;
    *(uint32_t*)(g_Wh + k * TILE_GB + off) =
        ((uint32_t)__half_as_ushort(h1) << 16) | __half_as_ushort(h0);
}

// ================= HMMA branch kernel (single pass fp16, 2 CTAs/SM) =========
__global__ void __launch_bounds__(256, 2) k_branch() {
    extern __shared__ __align__(16) unsigned char sm[];
    const int A_OFF = 0;
    const int B_OFF = A_OFF + 128 * PITCH * 2;
    uint32_t sb = smem_u32(sm);
    int tid = threadIdx.x;
    int w = tid >> 5, lane = tid & 31;
    int n0 = blockIdx.x * 128;

    for (int idx = tid; idx < 128 * 64; idx += 256) {
        int row = idx >> 6, c2 = idx & 63;
        uint32_t v = (n0 + row < NN) ? g_yh[(size_t)(n0 + row) * 64 + c2] : 0u;
        *(uint32_t*)(sm + A_OFF + row * (PITCH * 2) + c2 * 4) = v;
    }

    int a_row = lane & 15, a_cb = (lane >> 4) * 8;
    int b_row = ((lane >> 4) * 8) + (lane & 7);
    int b_kb = ((lane >> 3) & 1) * 8;
    const float4* bmt = (const float4*)g_BM;

    for (int k = 0; k < 7; k++) {
        __syncthreads();
        {
            const uint4* sh = (const uint4*)(g_Wh + k * TILE_GB);
            for (int i = tid; i < 2048; i += 256) {
                int f = i >> 4, seg = i & 15;
                *(uint4*)(sm + B_OFF + f * (PITCH * 2) + seg * 16) = sh[i];
            }
        }
        __syncthreads();

        float acc[16][4];
        #pragma unroll
        for (int t = 0; t < 16; t++)
            #pragma unroll
            for (int j = 0; j < 4; j++) acc[t][j] = 0.f;

        #pragma unroll
        for (int ks = 0; ks < 8; ks++) {
            uint32_t a0, a1, a2, a3;
            uint32_t aaddr = sb + A_OFF + (w * 16 + a_row) * (PITCH * 2) + (ks * 16 + a_cb) * 2;
            asm volatile("ldmatrix.sync.aligned.m8n8.x4.shared.b16 {%0,%1,%2,%3}, [%4];"
                         : "=r"(a0), "=r"(a1), "=r"(a2), "=r"(a3) : "r"(aaddr));
            #pragma unroll
            for (int p = 0; p < 8; p++) {
                uint32_t b0, b1, b2, b3;
                uint32_t baddr = sb + B_OFF + (p * 16 + b_row) * (PITCH * 2) + (ks * 16 + b_kb) * 2;
                asm volatile("ldmatrix.sync.aligned.m8n8.x4.shared.b16 {%0,%1,%2,%3}, [%4];"
                             : "=r"(b0), "=r"(b1), "=r"(b2), "=r"(b3) : "r"(baddr));
                asm volatile(
                    "mma.sync.aligned.m16n8k16.row.col.f32.f16.f16.f32 "
                    "{%0,%1,%2,%3}, {%4,%5,%6,%7}, {%8,%9}, {%0,%1,%2,%3};"
                    : "+f"(acc[2*p][0]), "+f"(acc[2*p][1]), "+f"(acc[2*p][2]), "+f"(acc[2*p][3])
                    : "r"(a0), "r"(a1), "r"(a2), "r"(a3), "r"(b0), "r"(b1));
                asm volatile(
                    "mma.sync.aligned.m16n8k16.row.col.f32.f16.f16.f32 "
                    "{%0,%1,%2,%3}, {%4,%5,%6,%7}, {%8,%9}, {%0,%1,%2,%3};"
                    : "+f"(acc[2*p+1][0]), "+f"(acc[2*p+1][1]), "+f"(acc[2*p+1][2]), "+f"(acc[2*p+1][3])
                    : "r"(a0), "r"(a1), "r"(a2), "r"(a3), "r"(b2), "r"(b3));
            }
        }

        int gr = lane >> 2, cq = (lane & 3) * 2;
        float zA0 = 0.f, zA1 = 0.f, zA2 = 0.f, zB0 = 0.f, zB1 = 0.f, zB2 = 0.f;
        #pragma unroll
        for (int nt = 0; nt < 16; nt++) {
            float4 m0 = __ldg(&bmt[k * HH + nt * 8 + cq]);
            float4 m1 = __ldg(&bmt[k * HH + nt * 8 + cq + 1]);
            float hA0 = fmaxf(acc[nt][0] + m0.x, 0.f);
            float hA1 = fmaxf(acc[nt][1] + m1.x, 0.f);
            float hB0 = fmaxf(acc[nt][2] + m0.x, 0.f);
            float hB1 = fmaxf(acc[nt][3] + m1.x, 0.f);
            zA0 = fmaf(hA0, m0.y, fmaf(hA1, m1.y, zA0));
            zA1 = fmaf(hA0, m0.z, fmaf(hA1, m1.z, zA1));
            zA2 = fmaf(hA0, m0.w, fmaf(hA1, m1.w, zA2));
            zB0 = fmaf(hB0, m0.y, fmaf(hB1, m1.y, zB0));
            zB1 = fmaf(hB0, m0.z, fmaf(hB1, m1.z, zB1));
            zB2 = fmaf(hB0, m0.w, fmaf(hB1, m1.w, zB2));
        }
        #pragma unroll
        for (int off = 1; off < 4; off <<= 1) {
            zA0 += __shfl_xor_sync(0xffffffffu, zA0, off);
            zA1 += __shfl_xor_sync(0xffffffffu, zA1, off);
            zA2 += __shfl_xor_sync(0xffffffffu, zA2, off);
            zB0 += __shfl_xor_sync(0xffffffffu, zB0, off);
            zB1 += __shfl_xor_sync(0xffffffffu, zB1, off);
            zB2 += __shfl_xor_sync(0xffffffffu, zB2, off);
        }
        if ((lane & 3) == 0) {
            int colbase = (k < 5) ? 3 * k : 15 + 2 * (k - 5);
            int ncol = (k < 5) ? 3 : 2;
            int rowA = n0 + w * 16 + gr, rowB = rowA + 8;
            if (rowA < NN) {
                float di = g_dinv[rowA];
                __half* zp = &g_Zh[(size_t)rowA * ZC + colbase];
                zp[0] = __float2half_rn(zA0 * di);
                zp[1] = __float2half_rn(zA1 * di);
                if (ncol == 3) zp[2] = __float2half_rn(zA2 * di);
            }
            if (rowB < NN) {
                float di = g_dinv[rowB];
                __half* zp = &g_Zh[(size_t)rowB * ZC + colbase];
                zp[0] = __float2half_rn(zB0 * di);
                zp[1] = __float2half_rn(zB1 * di);
                if (ncol == 3) zp[2] = __float2half_rn(zB2 * di);
            }
        }
    }
}

// ================= fused CSR-aggregate + softmax (warp per node) =================
__global__ void k_softmax_fused(float* __restrict__ out) {
    int n = (blockIdx.x * blockDim.x + threadIdx.x) >> 5;
    int lane = threadIdx.x & 31;
    if (n >= NN) return;
    bool active = lane < 19;
    int zlane = active ? lane : 0;
    float acc = active ? __half2float(g_Zh[(size_t)n * ZC + lane]) : 0.f;
    int end = g_row[n], e = end - g_cnt[n];
    for (; e + 3 < end; e += 4) {
        int s0 = g_srcl[e], s1 = g_srcl[e + 1], s2 = g_srcl[e + 2], s3 = g_srcl[e + 3];
        float v0 = __half2float(g_Zh[(size_t)s0 * ZC + zlane]);
        float v1 = __half2float(g_Zh[(size_t)s1 * ZC + zlane]);
        float v2 = __half2float(g_Zh[(size_t)s2 * ZC + zlane]);
        float v3 = __half2float(g_Zh[(size_t)s3 * ZC + zlane]);
        acc += (v0 + v1) + (v2 + v3);
    }
    for (; e < end; e++) {
        int s0 = g_srcl[e];
        acc += __half2float(g_Zh[(size_t)s0 * ZC + zlane]);
    }
    float di = g_dinv[n];
    float p = active ? fmaf(acc, di, g_c[lane]) : -1e30f;

    int base, ncol, j;
    if (lane < 15) { base = lane - (lane % 3); ncol = 3; j = lane - base; }
    else { base = 15 + ((lane - 15) & ~1); ncol = 2; j = lane - base; }
    float v0 = __shfl_sync(0xffffffffu, p, base);
    float v1 = __shfl_sync(0xffffffffu, p, base + 1);
    float v2 = (ncol == 3) ? __shfl_sync(0xffffffffu, p, base + 2) : -1e30f;
    float m = fmaxf(v0, fmaxf(v1, v2));
    float sum = __expf(v0 - m) + __expf(v1 - m) + ((ncol == 3) ? __expf(v2 - m) : 0.f);
    float mine = __expf(p - m) / sum;
    if (active)
        out[(long)base * NN + (long)n * ncol + j] = mine;
}

extern "C" void kernel_launch(void* const* d_in, const int* in_sizes, int n_in,
                              void* d_out, int out_size) {
    const float* x   = (const float*)d_in[0];
    const int*   ei  = (const int*)d_in[1];
    const float* gw_ = (const float*)d_in[2];
    const float* gb  = (const float*)d_in[3];
    const float* r3w = (const float*)d_in[4];
    const float* r3b = (const float*)d_in[5];
    const float* r2w = (const float*)d_in[6];
    const float* r2b = (const float*)d_in[7];
    float* out = (float*)d_out;

    const int SMEM = 2 * 128 * PITCH * 2;   // 69632
    static int once = 0;
    if (!once) {
        cudaFuncSetAttribute(k_branch, cudaFuncAttributeMaxDynamicSharedMemorySize, SMEM);
        once = 1;
    }

    // CSR build
    k_init<<<(NN + 255) / 256, 256>>>();
    k_count<<<(NE / 4 + 255) / 256, 256>>>((const int4*)(ei + NE));
    k_scan1<<<NSCAN, SCAN_BLK>>>();
    k_scan2<<<1, 32>>>();
    k_scan3<<<(NN + 255) / 256, 256>>>();
    k_scatter<<<(NE + 255) / 256, 256>>>(ei);
    // fp16 conversions + weight prep
    k_xh<<<(NN * 32 + 255) / 256, 256>>>((const float4*)x);
    k_mc<<<(19 * HH + 127) / 128, 128>>>(gw_, gb, r3w, r3b, r2w, r2b);
    k_prep_w<<<(7 * 128 * 64 + 127) / 128, 128>>>(gw_);
    // main pipeline
    k_agg_y_csr<<<(NN * 32 + 255) / 256, 256>>>();
    k_branch<<<NB, 256, SMEM>>>();
    k_softmax_fused<<<(NN * 32 + 255) / 256, 256>>>(out);
}